// round 12
// baseline (speedup 1.0000x reference)
#include <cuda_runtime.h>
#include <cstdint>

#define NNODES 50000
#define NEDGES 800000

// ---------------- scratch (device globals; no allocation allowed) ----------
__device__ float g_fs[NNODES * 128];
__device__ float g_fd[NNODES * 128];
__device__ float g_h [NNODES * 128];
__device__ int   g_hist[NNODES];
__device__ int   g_rowptr[NNODES + 1];
__device__ int   g_woff[NNODES];
__device__ int   g_ssrc[NEDGES];

__device__ __forceinline__ float lrelu(float x) { return x > 0.f ? x : 0.2f * x; }

// ---- packed f32x2 helpers (FFMA2 path — not reachable from plain C++) -----
__device__ __forceinline__ unsigned long long pack2(float lo, float hi) {
    unsigned long long r;
    asm("mov.b64 %0, {%1, %2};" : "=l"(r) : "f"(lo), "f"(hi));
    return r;
}
__device__ __forceinline__ void unpack2(unsigned long long v, float& lo, float& hi) {
    asm("mov.b64 {%0, %1}, %2;" : "=f"(lo), "=f"(hi) : "l"(v));
}
__device__ __forceinline__ unsigned long long fma2(unsigned long long a,
                                                   unsigned long long b,
                                                   unsigned long long c) {
    unsigned long long d;
    asm("fma.rn.f32x2 %0, %1, %2, %3;" : "=l"(d) : "l"(a), "l"(b), "l"(c));
    return d;
}

// ================= CSR construction (once per launch, reused 3x) ============
__global__ void hist_count4(const int* __restrict__ dst, int* hist, int E4) {
    int i = blockIdx.x * blockDim.x + threadIdx.x;
    if (i < E4) {
        int4 d = reinterpret_cast<const int4*>(dst)[i];
        atomicAdd(&hist[d.x], 1);
        atomicAdd(&hist[d.y], 1);
        atomicAdd(&hist[d.z], 1);
        atomicAdd(&hist[d.w], 1);
    }
}
__global__ void scan_hist(const int* __restrict__ hist, int* rowptr, int* woff, int n) {
    __shared__ int sums[1024];
    const int t = threadIdx.x;
    const int chunk = (n + 1023) / 1024;
    const int begin = t * chunk;
    const int end   = min(begin + chunk, n);
    int s = 0;
    for (int i = begin; i < end; i++) s += hist[i];
    sums[t] = s;
    __syncthreads();
    for (int d = 1; d < 1024; d <<= 1) {
        int v = (t >= d) ? sums[t - d] : 0;
        __syncthreads();
        sums[t] += v;
        __syncthreads();
    }
    int off = sums[t] - s;   // exclusive prefix
    for (int i = begin; i < end; i++) {
        rowptr[i] = off;
        woff[i]   = off;
        off += hist[i];
    }
    if (end == n && begin <= n) rowptr[n] = off;
}
__global__ void edge_bucket4(const int* __restrict__ src, const int* __restrict__ dst,
                             int* woff, int* ssrc, int E4) {
    int i = blockIdx.x * blockDim.x + threadIdx.x;
    if (i < E4) {
        int4 d = reinterpret_cast<const int4*>(dst)[i];
        int4 s = reinterpret_cast<const int4*>(src)[i];
        int p0 = atomicAdd(&woff[d.x], 1);
        int p1 = atomicAdd(&woff[d.y], 1);
        int p2 = atomicAdd(&woff[d.z], 1);
        int p3 = atomicAdd(&woff[d.w], 1);
        ssrc[p0] = s.x;
        ssrc[p1] = s.y;
        ssrc[p2] = s.z;
        ssrc[p3] = s.w;
    }
}

// ---------------- dual GEMM (FFMA2): C0 = act(A)@W0+b0 ; C1 = act(A)@W1+b1 --
// Tile config = best measured (TM=8, TN=4, BM=32, 3 CTAs/SM). NEW: lane->tile
// mapping tx = t/TROWS, ty = t%TROWS so warp lanes SHARE tx in groups of
// TROWS -> W LDS.128 dedups to 1 wavefront (was 4). A stays cheap.
template<int BN, int TM, int TN, int MAXB>
__global__ void __launch_bounds__(256, MAXB)
gemm_dual_k128(const float* __restrict__ A,
               const float* __restrict__ W0, const float* __restrict__ b0,
               const float* __restrict__ W1, const float* __restrict__ b1,
               float* __restrict__ C0, float* __restrict__ C1,
               int N, int relu_in)
{
    constexpr int K = 128, KC = 32;
    constexpr int TCOLS = (2 * BN) / TN;
    constexpr int TROWS = 256 / TCOLS;
    constexpr int BM = TROWS * TM;
    static_assert(TM % 4 == 0 && TN % 4 == 0, "vectorized tiling");

    __shared__ __align__(16) float As[KC][BM + 4];
    __shared__ __align__(16) float Wsm[KC][2 * BN];

    const int t  = threadIdx.x;
    const int tx = t / TROWS;     // warp-shared in groups of TROWS -> W broadcast
    const int ty = t % TROWS;
    const int rowBase = blockIdx.x * BM;

    unsigned long long acc2[TM / 2][TN];
    #pragma unroll
    for (int i = 0; i < TM / 2; i++)
        #pragma unroll
        for (int j = 0; j < TN; j++) acc2[i][j] = 0ull;

    for (int kc = 0; kc < K; kc += KC) {
        #pragma unroll
        for (int i = 0; i < (BM * KC) / (256 * 4); ++i) {
            int fi = t + i * 256;
            int r  = fi / (KC / 4);
            int c4 = fi % (KC / 4);
            int gr = rowBase + r;
            float4 v = make_float4(0.f, 0.f, 0.f, 0.f);
            if (gr < N) {
                v = reinterpret_cast<const float4*>(A + (size_t)gr * K + kc)[c4];
                if (relu_in) {
                    v.x = fmaxf(v.x, 0.f); v.y = fmaxf(v.y, 0.f);
                    v.z = fmaxf(v.z, 0.f); v.w = fmaxf(v.w, 0.f);
                }
            }
            As[c4 * 4 + 0][r] = v.x;
            As[c4 * 4 + 1][r] = v.y;
            As[c4 * 4 + 2][r] = v.z;
            As[c4 * 4 + 3][r] = v.w;
        }
        #pragma unroll
        for (int i = 0; i < (KC * 2 * BN) / (256 * 4); ++i) {
            int fi = t + i * 256;
            int r  = fi / ((2 * BN) / 4);
            int c4 = fi % ((2 * BN) / 4);
            int col = c4 * 4;
            float4 v;
            if (col < BN) v = reinterpret_cast<const float4*>(W0 + (size_t)(kc + r) * BN + col)[0];
            else          v = reinterpret_cast<const float4*>(W1 + (size_t)(kc + r) * BN + (col - BN))[0];
            reinterpret_cast<float4*>(&Wsm[r][0])[c4] = v;
        }
        __syncthreads();

        #pragma unroll
        for (int k = 0; k < KC; k++) {
            unsigned long long ap[TM / 2];
            #pragma unroll
            for (int i = 0; i < TM / 4; i++) {
                ulonglong2 q = *reinterpret_cast<const ulonglong2*>(&As[k][ty * TM + i * 4]);
                ap[i * 2 + 0] = q.x;
                ap[i * 2 + 1] = q.y;
            }
            unsigned long long wd[TN];
            #pragma unroll
            for (int j = 0; j < TN / 4; j++) {
                float4 w = *reinterpret_cast<const float4*>(&Wsm[k][tx * TN + j * 4]);
                wd[j * 4 + 0] = pack2(w.x, w.x);
                wd[j * 4 + 1] = pack2(w.y, w.y);
                wd[j * 4 + 2] = pack2(w.z, w.z);
                wd[j * 4 + 3] = pack2(w.w, w.w);
            }
            #pragma unroll
            for (int i = 0; i < TM / 2; i++)
                #pragma unroll
                for (int j = 0; j < TN; j++)
                    acc2[i][j] = fma2(ap[i], wd[j], acc2[i][j]);
        }
        __syncthreads();
    }

    const int half = (tx * TN) / BN;
    const int col  = (tx * TN) % BN;
    float*       C  = half ? C1 : C0;
    const float* bb = half ? b1 : b0;
    float bias[TN];
    #pragma unroll
    for (int j = 0; j < TN; j++) bias[j] = bb[col + j];

    #pragma unroll
    for (int i = 0; i < TM / 2; i++) {
        float lo[TN], hi[TN];
        #pragma unroll
        for (int j = 0; j < TN; j++) unpack2(acc2[i][j], lo[j], hi[j]);
        int gr0 = rowBase + ty * TM + 2 * i;
        int gr1 = gr0 + 1;
        if (gr0 < N) {
            #pragma unroll
            for (int j = 0; j < TN / 4; j++) {
                float4 o = make_float4(lo[j*4+0] + bias[j*4+0], lo[j*4+1] + bias[j*4+1],
                                       lo[j*4+2] + bias[j*4+2], lo[j*4+3] + bias[j*4+3]);
                *reinterpret_cast<float4*>(C + (size_t)gr0 * BN + col + j * 4) = o;
            }
        }
        if (gr1 < N) {
            #pragma unroll
            for (int j = 0; j < TN / 4; j++) {
                float4 o = make_float4(hi[j*4+0] + bias[j*4+0], hi[j*4+1] + bias[j*4+1],
                                       hi[j*4+2] + bias[j*4+2], hi[j*4+3] + bias[j*4+3]);
                *reinterpret_cast<float4*>(C + (size_t)gr1 * BN + col + j * 4) = o;
            }
        }
    }
}

// ========== CSR edge aggregation, H=4: warp per dst, prefetch depth 2 =======
// (exact R6 structure — best measured edge kernel; do not touch)
__global__ void edge_csr4(const int* __restrict__ rowptr, const int* __restrict__ ssrc,
                          const float* __restrict__ fs, const float* __restrict__ fd,
                          const float* __restrict__ a, float* __restrict__ out, int N)
{
    const int lane = threadIdx.x & 31;
    const int d    = (blockIdx.x * blockDim.x + threadIdx.x) >> 5;
    if (d >= N) return;

    const float4* fs4 = reinterpret_cast<const float4*>(fs);
    float4 v  = reinterpret_cast<const float4*>(fd)[(size_t)d * 32 + lane];
    float4 av = reinterpret_cast<const float4*>(a)[lane];

    float4 acc = make_float4(0.f, 0.f, 0.f, 0.f);
    float den = 0.f;

    const int start = rowptr[d];
    const int end   = rowptr[d + 1];
    if (start < end) {
        const int last = end - 1;
        int i1 = min(start + 1, last);
        float4 u0 = fs4[(size_t)__ldg(ssrc + start) * 32 + lane];
        float4 u1 = fs4[(size_t)__ldg(ssrc + i1)    * 32 + lane];
        for (int i = start; i < end; i++) {
            float4 u = u0;
            u0 = u1;
            int nx = min(i + 2, last);                 // clamped prefetch (depth 2)
            u1 = fs4[(size_t)__ldg(ssrc + nx) * 32 + lane];
            float p = lrelu(u.x + v.x) * av.x + lrelu(u.y + v.y) * av.y
                    + lrelu(u.z + v.z) * av.z + lrelu(u.w + v.w) * av.w;
            p += __shfl_xor_sync(0xffffffffu, p, 1);
            p += __shfl_xor_sync(0xffffffffu, p, 2);
            p += __shfl_xor_sync(0xffffffffu, p, 4);
            float ex = __expf(p);    // softmax shift-invariant; logits are O(1)
            acc.x = fmaf(u.x, ex, acc.x);
            acc.y = fmaf(u.y, ex, acc.y);
            acc.z = fmaf(u.z, ex, acc.z);
            acc.w = fmaf(u.w, ex, acc.w);
            den += ex;
        }
    }
    float sc = (den > 0.f) ? 1.0f / den : 0.f;   // zero-degree -> zeros
    acc.x *= sc; acc.y *= sc; acc.z *= sc; acc.w *= sc;
    reinterpret_cast<float4*>(out)[(size_t)d * 32 + lane] = acc;
}

// ========== CSR edge aggregation, H=1 (32 feats): warp=dst, 4 edge slots ====
__global__ void edge_csr1(const int* __restrict__ rowptr, const int* __restrict__ ssrc,
                          const float* __restrict__ fs, const float* __restrict__ fd,
                          const float* __restrict__ a, float* __restrict__ out, int N)
{
    const int lane = threadIdx.x & 31;
    const int d    = (blockIdx.x * blockDim.x + threadIdx.x) >> 5;
    if (d >= N) return;
    const int slot = lane >> 3;
    const int sub  = lane & 7;

    const float4* fs4 = reinterpret_cast<const float4*>(fs);
    float4 v  = reinterpret_cast<const float4*>(fd)[(size_t)d * 8 + sub];
    float4 av = reinterpret_cast<const float4*>(a)[sub];

    float4 acc = make_float4(0.f, 0.f, 0.f, 0.f);
    float den = 0.f;

    const int start = rowptr[d];
    const int end   = rowptr[d + 1];
    const int iters = (end - start + 3) >> 2;

    int idx0 = start + slot;
    float4 un = make_float4(0.f, 0.f, 0.f, 0.f);
    if (idx0 < end) un = fs4[(size_t)__ldg(ssrc + idx0) * 8 + sub];

    for (int it = 0; it < iters; it++) {
        bool ok = (start + it * 4 + slot) < end;
        float4 u = un;
        int nidx = start + (it + 1) * 4 + slot;
        if (nidx < end) un = fs4[(size_t)__ldg(ssrc + nidx) * 8 + sub];
        else            un = make_float4(0.f, 0.f, 0.f, 0.f);

        float p = lrelu(u.x + v.x) * av.x + lrelu(u.y + v.y) * av.y
                + lrelu(u.z + v.z) * av.z + lrelu(u.w + v.w) * av.w;
        p += __shfl_xor_sync(0xffffffffu, p, 1);
        p += __shfl_xor_sync(0xffffffffu, p, 2);
        p += __shfl_xor_sync(0xffffffffu, p, 4);
        float ex = ok ? __expf(p) : 0.f;
        acc.x = fmaf(u.x, ex, acc.x);
        acc.y = fmaf(u.y, ex, acc.y);
        acc.z = fmaf(u.z, ex, acc.z);
        acc.w = fmaf(u.w, ex, acc.w);
        den += ex;
    }
    #pragma unroll
    for (int m = 8; m <= 16; m <<= 1) {
        acc.x += __shfl_xor_sync(0xffffffffu, acc.x, m);
        acc.y += __shfl_xor_sync(0xffffffffu, acc.y, m);
        acc.z += __shfl_xor_sync(0xffffffffu, acc.z, m);
        acc.w += __shfl_xor_sync(0xffffffffu, acc.w, m);
        den   += __shfl_xor_sync(0xffffffffu, den,   m);
    }
    if (slot == 0) {
        float sc = (den > 0.f) ? 1.0f / den : 0.f;
        acc.x *= sc; acc.y *= sc; acc.z *= sc; acc.w *= sc;
        reinterpret_cast<float4*>(out)[(size_t)d * 8 + sub] = acc;
    }
}

// ---------------- launch -----------------------------------------------------
extern "C" void kernel_launch(void* const* d_in, const int* in_sizes, int n_in,
                              void* d_out, int out_size)
{
    const float* feat = (const float*)d_in[0];
    const int*   src  = (const int*)d_in[1];
    const int*   dst  = (const int*)d_in[2];
    const float* Ws0 = (const float*)d_in[3];  const float* bs0 = (const float*)d_in[4];
    const float* Wd0 = (const float*)d_in[5];  const float* bd0 = (const float*)d_in[6];
    const float* a0  = (const float*)d_in[7];
    const float* Ws1 = (const float*)d_in[8];  const float* bs1 = (const float*)d_in[9];
    const float* Wd1 = (const float*)d_in[10]; const float* bd1 = (const float*)d_in[11];
    const float* a1  = (const float*)d_in[12];
    const float* Ws2 = (const float*)d_in[13]; const float* bs2 = (const float*)d_in[14];
    const float* Wd2 = (const float*)d_in[15]; const float* bd2 = (const float*)d_in[16];
    const float* a2  = (const float*)d_in[17];
    float* out = (float*)d_out;

    const int N = in_sizes[0] / 128;
    const int E = in_sizes[1];

    float *fs, *fd, *h;
    int *hist, *rowptr, *woff, *ssrc;
    cudaGetSymbolAddress((void**)&fs,     g_fs);
    cudaGetSymbolAddress((void**)&fd,     g_fd);
    cudaGetSymbolAddress((void**)&h,      g_h);
    cudaGetSymbolAddress((void**)&hist,   g_hist);
    cudaGetSymbolAddress((void**)&rowptr, g_rowptr);
    cudaGetSymbolAddress((void**)&woff,   g_woff);
    cudaGetSymbolAddress((void**)&ssrc,   g_ssrc);

    const int gemmGridBig   = (N + 31) / 32;   // BM=32 (TM=8, TN=4, 3 CTAs)
    const int gemmGridSmall = (N + 63) / 64;   // BM=64 (TM=4, TN=4)
    const int edgeGrid = (N * 32 + 255) / 256; // one warp per dst
    const int E4 = E / 4;
    const int eg4 = (E4 + 255) / 256;

    // ---- CSR build (src/dst constant across layers; reused 3x) ----
    cudaMemsetAsync(hist, 0, (size_t)N * sizeof(int));
    hist_count4<<<eg4, 256>>>(dst, hist, E4);
    scan_hist<<<1, 1024>>>(hist, rowptr, woff, N);
    edge_bucket4<<<eg4, 256>>>(src, dst, woff, ssrc, E4);

    // ---- layer 0 (input 128 -> 4x32) ----
    gemm_dual_k128<128, 8, 4, 3><<<gemmGridBig, 256>>>(feat, Ws0, bs0, Wd0, bd0, fs, fd, N, 0);
    edge_csr4<<<edgeGrid, 256>>>(rowptr, ssrc, fs, fd, a0, h, N);

    // ---- layer 1 (ReLU(h) 128 -> 4x32) ----
    gemm_dual_k128<128, 8, 4, 3><<<gemmGridBig, 256>>>(h, Ws1, bs1, Wd1, bd1, fs, fd, N, 1);
    edge_csr4<<<edgeGrid, 256>>>(rowptr, ssrc, fs, fd, a1, h, N);

    // ---- layer 2 (ReLU(h) 128 -> 1x32), mean over 1 head == identity ----
    gemm_dual_k128<32, 4, 4, 2><<<gemmGridSmall, 256>>>(h, Ws2, bs2, Wd2, bd2, fs, fd, N, 1);
    edge_csr1<<<edgeGrid, 256>>>(rowptr, ssrc, fs, fd, a2, out, N);
}

// round 13
// speedup vs baseline: 1.0511x; 1.0511x over previous
#include <cuda_runtime.h>
#include <cstdint>

#define NNODES 50000
#define NEDGES 800000

// ---------------- scratch (device globals; no allocation allowed) ----------
__device__ float g_fs[NNODES * 128];
__device__ float g_fd[NNODES * 128];
__device__ float g_h [NNODES * 128];
__device__ int   g_hist[NNODES];
__device__ int   g_rowptr[NNODES + 1];
__device__ int   g_woff[NNODES];
__device__ int   g_ssrc[NEDGES];

__device__ __forceinline__ float lrelu(float x) { return x > 0.f ? x : 0.2f * x; }

// ---- packed f32x2 helpers (FFMA2 path — not reachable from plain C++) -----
__device__ __forceinline__ unsigned long long pack2(float lo, float hi) {
    unsigned long long r;
    asm("mov.b64 %0, {%1, %2};" : "=l"(r) : "f"(lo), "f"(hi));
    return r;
}
__device__ __forceinline__ void unpack2(unsigned long long v, float& lo, float& hi) {
    asm("mov.b64 {%0, %1}, %2;" : "=f"(lo), "=f"(hi) : "l"(v));
}
__device__ __forceinline__ unsigned long long fma2(unsigned long long a,
                                                   unsigned long long b,
                                                   unsigned long long c) {
    unsigned long long d;
    asm("fma.rn.f32x2 %0, %1, %2, %3;" : "=l"(d) : "l"(a), "l"(b), "l"(c));
    return d;
}

// ================= CSR construction (once per launch, reused 3x) ============
__global__ void hist_count4(const int* __restrict__ dst, int* hist, int E4) {
    int i = blockIdx.x * blockDim.x + threadIdx.x;
    if (i < E4) {
        int4 d = reinterpret_cast<const int4*>(dst)[i];
        atomicAdd(&hist[d.x], 1);
        atomicAdd(&hist[d.y], 1);
        atomicAdd(&hist[d.z], 1);
        atomicAdd(&hist[d.w], 1);
    }
}
__global__ void scan_hist(const int* __restrict__ hist, int* rowptr, int* woff, int n) {
    __shared__ int sums[1024];
    const int t = threadIdx.x;
    const int chunk = (n + 1023) / 1024;
    const int begin = t * chunk;
    const int end   = min(begin + chunk, n);
    int s = 0;
    for (int i = begin; i < end; i++) s += hist[i];
    sums[t] = s;
    __syncthreads();
    for (int d = 1; d < 1024; d <<= 1) {
        int v = (t >= d) ? sums[t - d] : 0;
        __syncthreads();
        sums[t] += v;
        __syncthreads();
    }
    int off = sums[t] - s;   // exclusive prefix
    for (int i = begin; i < end; i++) {
        rowptr[i] = off;
        woff[i]   = off;
        off += hist[i];
    }
    if (end == n && begin <= n) rowptr[n] = off;
}
__global__ void edge_bucket4(const int* __restrict__ src, const int* __restrict__ dst,
                             int* woff, int* ssrc, int E4) {
    int i = blockIdx.x * blockDim.x + threadIdx.x;
    if (i < E4) {
        int4 d = reinterpret_cast<const int4*>(dst)[i];
        int4 s = reinterpret_cast<const int4*>(src)[i];
        int p0 = atomicAdd(&woff[d.x], 1);
        int p1 = atomicAdd(&woff[d.y], 1);
        int p2 = atomicAdd(&woff[d.z], 1);
        int p3 = atomicAdd(&woff[d.w], 1);
        ssrc[p0] = s.x;
        ssrc[p1] = s.y;
        ssrc[p2] = s.z;
        ssrc[p3] = s.w;
    }
}

// ---------------- dual GEMM (FFMA2): C0 = act(A)@W0+b0 ; C1 = act(A)@W1+b1 --
// Tile = best measured (TM=8, TN=4, BM=32, 3 CTAs/SM).
// WARP2D=1: 2-D warp tiling — tx = warp*8+(lane&7), ty = lane>>3.
//   W LDS: 8 distinct x 16B = 128B contiguous -> 1 wavefront (was 4)
//   A LDS: 4 distinct x 16B @32B stride -> conflict-free, 1 wf/load (unchanged)
//   Epilogue: 8 lanes x 16B contiguous per row-group (stays coalesced)
template<int BN, int TM, int TN, int MAXB, int WARP2D>
__global__ void __launch_bounds__(256, MAXB)
gemm_dual_k128(const float* __restrict__ A,
               const float* __restrict__ W0, const float* __restrict__ b0,
               const float* __restrict__ W1, const float* __restrict__ b1,
               float* __restrict__ C0, float* __restrict__ C1,
               int N, int relu_in)
{
    constexpr int K = 128, KC = 32;
    constexpr int TCOLS = (2 * BN) / TN;
    constexpr int TROWS = 256 / TCOLS;
    constexpr int BM = TROWS * TM;
    static_assert(TM % 4 == 0 && TN % 4 == 0, "vectorized tiling");

    __shared__ __align__(16) float As[KC][BM + 4];
    __shared__ __align__(16) float Wsm[KC][2 * BN];

    const int t  = threadIdx.x;
    int tx, ty;
    if (WARP2D) {
        const int lane = t & 31;
        const int warp = t >> 5;
        tx = warp * 8 + (lane & 7);   // 64 col-groups, warp-contiguous W reads
        ty = lane >> 3;               // 4 row-groups
    } else {
        tx = t % TCOLS;
        ty = t / TCOLS;
    }
    const int rowBase = blockIdx.x * BM;

    unsigned long long acc2[TM / 2][TN];
    #pragma unroll
    for (int i = 0; i < TM / 2; i++)
        #pragma unroll
        for (int j = 0; j < TN; j++) acc2[i][j] = 0ull;

    for (int kc = 0; kc < K; kc += KC) {
        #pragma unroll
        for (int i = 0; i < (BM * KC) / (256 * 4); ++i) {
            int fi = t + i * 256;
            int r  = fi / (KC / 4);
            int c4 = fi % (KC / 4);
            int gr = rowBase + r;
            float4 v = make_float4(0.f, 0.f, 0.f, 0.f);
            if (gr < N) {
                v = reinterpret_cast<const float4*>(A + (size_t)gr * K + kc)[c4];
                if (relu_in) {
                    v.x = fmaxf(v.x, 0.f); v.y = fmaxf(v.y, 0.f);
                    v.z = fmaxf(v.z, 0.f); v.w = fmaxf(v.w, 0.f);
                }
            }
            As[c4 * 4 + 0][r] = v.x;
            As[c4 * 4 + 1][r] = v.y;
            As[c4 * 4 + 2][r] = v.z;
            As[c4 * 4 + 3][r] = v.w;
        }
        #pragma unroll
        for (int i = 0; i < (KC * 2 * BN) / (256 * 4); ++i) {
            int fi = t + i * 256;
            int r  = fi / ((2 * BN) / 4);
            int c4 = fi % ((2 * BN) / 4);
            int col = c4 * 4;
            float4 v;
            if (col < BN) v = reinterpret_cast<const float4*>(W0 + (size_t)(kc + r) * BN + col)[0];
            else          v = reinterpret_cast<const float4*>(W1 + (size_t)(kc + r) * BN + (col - BN))[0];
            reinterpret_cast<float4*>(&Wsm[r][0])[c4] = v;
        }
        __syncthreads();

        #pragma unroll
        for (int k = 0; k < KC; k++) {
            unsigned long long ap[TM / 2];
            #pragma unroll
            for (int i = 0; i < TM / 4; i++) {
                ulonglong2 q = *reinterpret_cast<const ulonglong2*>(&As[k][ty * TM + i * 4]);
                ap[i * 2 + 0] = q.x;
                ap[i * 2 + 1] = q.y;
            }
            unsigned long long wd[TN];
            #pragma unroll
            for (int j = 0; j < TN / 4; j++) {
                float4 w = *reinterpret_cast<const float4*>(&Wsm[k][tx * TN + j * 4]);
                wd[j * 4 + 0] = pack2(w.x, w.x);
                wd[j * 4 + 1] = pack2(w.y, w.y);
                wd[j * 4 + 2] = pack2(w.z, w.z);
                wd[j * 4 + 3] = pack2(w.w, w.w);
            }
            #pragma unroll
            for (int i = 0; i < TM / 2; i++)
                #pragma unroll
                for (int j = 0; j < TN; j++)
                    acc2[i][j] = fma2(ap[i], wd[j], acc2[i][j]);
        }
        __syncthreads();
    }

    const int half = (tx * TN) / BN;
    const int col  = (tx * TN) % BN;
    float*       C  = half ? C1 : C0;
    const float* bb = half ? b1 : b0;
    float bias[TN];
    #pragma unroll
    for (int j = 0; j < TN; j++) bias[j] = bb[col + j];

    #pragma unroll
    for (int i = 0; i < TM / 2; i++) {
        float lo[TN], hi[TN];
        #pragma unroll
        for (int j = 0; j < TN; j++) unpack2(acc2[i][j], lo[j], hi[j]);
        int gr0 = rowBase + ty * TM + 2 * i;
        int gr1 = gr0 + 1;
        if (gr0 < N) {
            #pragma unroll
            for (int j = 0; j < TN / 4; j++) {
                float4 o = make_float4(lo[j*4+0] + bias[j*4+0], lo[j*4+1] + bias[j*4+1],
                                       lo[j*4+2] + bias[j*4+2], lo[j*4+3] + bias[j*4+3]);
                *reinterpret_cast<float4*>(C + (size_t)gr0 * BN + col + j * 4) = o;
            }
        }
        if (gr1 < N) {
            #pragma unroll
            for (int j = 0; j < TN / 4; j++) {
                float4 o = make_float4(hi[j*4+0] + bias[j*4+0], hi[j*4+1] + bias[j*4+1],
                                       hi[j*4+2] + bias[j*4+2], hi[j*4+3] + bias[j*4+3]);
                *reinterpret_cast<float4*>(C + (size_t)gr1 * BN + col + j * 4) = o;
            }
        }
    }
}

// ========== CSR edge aggregation, H=4: warp per dst, prefetch depth 2 =======
// (exact R6 structure — best measured edge kernel; do not touch)
__global__ void edge_csr4(const int* __restrict__ rowptr, const int* __restrict__ ssrc,
                          const float* __restrict__ fs, const float* __restrict__ fd,
                          const float* __restrict__ a, float* __restrict__ out, int N)
{
    const int lane = threadIdx.x & 31;
    const int d    = (blockIdx.x * blockDim.x + threadIdx.x) >> 5;
    if (d >= N) return;

    const float4* fs4 = reinterpret_cast<const float4*>(fs);
    float4 v  = reinterpret_cast<const float4*>(fd)[(size_t)d * 32 + lane];
    float4 av = reinterpret_cast<const float4*>(a)[lane];

    float4 acc = make_float4(0.f, 0.f, 0.f, 0.f);
    float den = 0.f;

    const int start = rowptr[d];
    const int end   = rowptr[d + 1];
    if (start < end) {
        const int last = end - 1;
        int i1 = min(start + 1, last);
        float4 u0 = fs4[(size_t)__ldg(ssrc + start) * 32 + lane];
        float4 u1 = fs4[(size_t)__ldg(ssrc + i1)    * 32 + lane];
        for (int i = start; i < end; i++) {
            float4 u = u0;
            u0 = u1;
            int nx = min(i + 2, last);                 // clamped prefetch (depth 2)
            u1 = fs4[(size_t)__ldg(ssrc + nx) * 32 + lane];
            float p = lrelu(u.x + v.x) * av.x + lrelu(u.y + v.y) * av.y
                    + lrelu(u.z + v.z) * av.z + lrelu(u.w + v.w) * av.w;
            p += __shfl_xor_sync(0xffffffffu, p, 1);
            p += __shfl_xor_sync(0xffffffffu, p, 2);
            p += __shfl_xor_sync(0xffffffffu, p, 4);
            float ex = __expf(p);    // softmax shift-invariant; logits are O(1)
            acc.x = fmaf(u.x, ex, acc.x);
            acc.y = fmaf(u.y, ex, acc.y);
            acc.z = fmaf(u.z, ex, acc.z);
            acc.w = fmaf(u.w, ex, acc.w);
            den += ex;
        }
    }
    float sc = (den > 0.f) ? 1.0f / den : 0.f;   // zero-degree -> zeros
    acc.x *= sc; acc.y *= sc; acc.z *= sc; acc.w *= sc;
    reinterpret_cast<float4*>(out)[(size_t)d * 32 + lane] = acc;
}

// ========== CSR edge aggregation, H=1 (32 feats): warp=dst, 4 edge slots ====
__global__ void edge_csr1(const int* __restrict__ rowptr, const int* __restrict__ ssrc,
                          const float* __restrict__ fs, const float* __restrict__ fd,
                          const float* __restrict__ a, float* __restrict__ out, int N)
{
    const int lane = threadIdx.x & 31;
    const int d    = (blockIdx.x * blockDim.x + threadIdx.x) >> 5;
    if (d >= N) return;
    const int slot = lane >> 3;
    const int sub  = lane & 7;

    const float4* fs4 = reinterpret_cast<const float4*>(fs);
    float4 v  = reinterpret_cast<const float4*>(fd)[(size_t)d * 8 + sub];
    float4 av = reinterpret_cast<const float4*>(a)[sub];

    float4 acc = make_float4(0.f, 0.f, 0.f, 0.f);
    float den = 0.f;

    const int start = rowptr[d];
    const int end   = rowptr[d + 1];
    const int iters = (end - start + 3) >> 2;

    int idx0 = start + slot;
    float4 un = make_float4(0.f, 0.f, 0.f, 0.f);
    if (idx0 < end) un = fs4[(size_t)__ldg(ssrc + idx0) * 8 + sub];

    for (int it = 0; it < iters; it++) {
        bool ok = (start + it * 4 + slot) < end;
        float4 u = un;
        int nidx = start + (it + 1) * 4 + slot;
        if (nidx < end) un = fs4[(size_t)__ldg(ssrc + nidx) * 8 + sub];
        else            un = make_float4(0.f, 0.f, 0.f, 0.f);

        float p = lrelu(u.x + v.x) * av.x + lrelu(u.y + v.y) * av.y
                + lrelu(u.z + v.z) * av.z + lrelu(u.w + v.w) * av.w;
        p += __shfl_xor_sync(0xffffffffu, p, 1);
        p += __shfl_xor_sync(0xffffffffu, p, 2);
        p += __shfl_xor_sync(0xffffffffu, p, 4);
        float ex = ok ? __expf(p) : 0.f;
        acc.x = fmaf(u.x, ex, acc.x);
        acc.y = fmaf(u.y, ex, acc.y);
        acc.z = fmaf(u.z, ex, acc.z);
        acc.w = fmaf(u.w, ex, acc.w);
        den += ex;
    }
    #pragma unroll
    for (int m = 8; m <= 16; m <<= 1) {
        acc.x += __shfl_xor_sync(0xffffffffu, acc.x, m);
        acc.y += __shfl_xor_sync(0xffffffffu, acc.y, m);
        acc.z += __shfl_xor_sync(0xffffffffu, acc.z, m);
        acc.w += __shfl_xor_sync(0xffffffffu, acc.w, m);
        den   += __shfl_xor_sync(0xffffffffu, den,   m);
    }
    if (slot == 0) {
        float sc = (den > 0.f) ? 1.0f / den : 0.f;
        acc.x *= sc; acc.y *= sc; acc.z *= sc; acc.w *= sc;
        reinterpret_cast<float4*>(out)[(size_t)d * 8 + sub] = acc;
    }
}

// ---------------- launch -----------------------------------------------------
extern "C" void kernel_launch(void* const* d_in, const int* in_sizes, int n_in,
                              void* d_out, int out_size)
{
    const float* feat = (const float*)d_in[0];
    const int*   src  = (const int*)d_in[1];
    const int*   dst  = (const int*)d_in[2];
    const float* Ws0 = (const float*)d_in[3];  const float* bs0 = (const float*)d_in[4];
    const float* Wd0 = (const float*)d_in[5];  const float* bd0 = (const float*)d_in[6];
    const float* a0  = (const float*)d_in[7];
    const float* Ws1 = (const float*)d_in[8];  const float* bs1 = (const float*)d_in[9];
    const float* Wd1 = (const float*)d_in[10]; const float* bd1 = (const float*)d_in[11];
    const float* a1  = (const float*)d_in[12];
    const float* Ws2 = (const float*)d_in[13]; const float* bs2 = (const float*)d_in[14];
    const float* Wd2 = (const float*)d_in[15]; const float* bd2 = (const float*)d_in[16];
    const float* a2  = (const float*)d_in[17];
    float* out = (float*)d_out;

    const int N = in_sizes[0] / 128;
    const int E = in_sizes[1];

    float *fs, *fd, *h;
    int *hist, *rowptr, *woff, *ssrc;
    cudaGetSymbolAddress((void**)&fs,     g_fs);
    cudaGetSymbolAddress((void**)&fd,     g_fd);
    cudaGetSymbolAddress((void**)&h,      g_h);
    cudaGetSymbolAddress((void**)&hist,   g_hist);
    cudaGetSymbolAddress((void**)&rowptr, g_rowptr);
    cudaGetSymbolAddress((void**)&woff,   g_woff);
    cudaGetSymbolAddress((void**)&ssrc,   g_ssrc);

    const int gemmGridBig   = (N + 31) / 32;   // BM=32 (TM=8, TN=4, 3 CTAs)
    const int gemmGridSmall = (N + 63) / 64;   // BM=64 (TM=4, TN=4)
    const int edgeGrid = (N * 32 + 255) / 256; // one warp per dst
    const int E4 = E / 4;
    const int eg4 = (E4 + 255) / 256;

    // ---- CSR build (src/dst constant across layers; reused 3x) ----
    cudaMemsetAsync(hist, 0, (size_t)N * sizeof(int));
    hist_count4<<<eg4, 256>>>(dst, hist, E4);
    scan_hist<<<1, 1024>>>(hist, rowptr, woff, N);
    edge_bucket4<<<eg4, 256>>>(src, dst, woff, ssrc, E4);

    // ---- layer 0 (input 128 -> 4x32) ----
    gemm_dual_k128<128, 8, 4, 3, 1><<<gemmGridBig, 256>>>(feat, Ws0, bs0, Wd0, bd0, fs, fd, N, 0);
    edge_csr4<<<edgeGrid, 256>>>(rowptr, ssrc, fs, fd, a0, h, N);

    // ---- layer 1 (ReLU(h) 128 -> 4x32) ----
    gemm_dual_k128<128, 8, 4, 3, 1><<<gemmGridBig, 256>>>(h, Ws1, bs1, Wd1, bd1, fs, fd, N, 1);
    edge_csr4<<<edgeGrid, 256>>>(rowptr, ssrc, fs, fd, a1, h, N);

    // ---- layer 2 (ReLU(h) 128 -> 1x32), mean over 1 head == identity ----
    gemm_dual_k128<32, 4, 4, 2, 0><<<gemmGridSmall, 256>>>(h, Ws2, bs2, Wd2, bd2, fs, fd, N, 1);
    edge_csr1<<<edgeGrid, 256>>>(rowptr, ssrc, fs, fd, a2, out, N);
}

// round 14
// speedup vs baseline: 1.0793x; 1.0268x over previous
#include <cuda_runtime.h>
#include <cstdint>

#define NNODES 50000
#define NEDGES 800000

// ---------------- scratch (device globals; no allocation allowed) ----------
__device__ float g_fs[NNODES * 128];
__device__ float g_fd[NNODES * 128];
__device__ float g_h [NNODES * 128];
__device__ int   g_hist[NNODES];
__device__ int   g_rowptr[NNODES + 1];
__device__ int   g_woff[NNODES];
__device__ int   g_ssrc[NEDGES];

__device__ __forceinline__ float lrelu(float x) { return x > 0.f ? x : 0.2f * x; }

// ---- packed f32x2 helpers (FFMA2 path — not reachable from plain C++) -----
__device__ __forceinline__ unsigned long long pack2(float lo, float hi) {
    unsigned long long r;
    asm("mov.b64 %0, {%1, %2};" : "=l"(r) : "f"(lo), "f"(hi));
    return r;
}
__device__ __forceinline__ void unpack2(unsigned long long v, float& lo, float& hi) {
    asm("mov.b64 {%0, %1}, %2;" : "=f"(lo), "=f"(hi) : "l"(v));
}
__device__ __forceinline__ unsigned long long fma2(unsigned long long a,
                                                   unsigned long long b,
                                                   unsigned long long c) {
    unsigned long long d;
    asm("fma.rn.f32x2 %0, %1, %2, %3;" : "=l"(d) : "l"(a), "l"(b), "l"(c));
    return d;
}

__device__ __forceinline__ void cp_async16(void* smem_dst, const void* gsrc) {
    unsigned saddr = (unsigned)__cvta_generic_to_shared(smem_dst);
    asm volatile("cp.async.cg.shared.global [%0], [%1], 16;"
                 :: "r"(saddr), "l"(gsrc) : "memory");
}
__device__ __forceinline__ void cp_async_commit() {
    asm volatile("cp.async.commit_group;" ::: "memory");
}
__device__ __forceinline__ void cp_async_wait_all() {
    asm volatile("cp.async.wait_group 0;" ::: "memory");
}

// ================= CSR construction (once per launch, reused 3x) ============
__global__ void hist_count4(const int* __restrict__ dst, int* hist, int E4) {
    int i = blockIdx.x * blockDim.x + threadIdx.x;
    if (i < E4) {
        int4 d = reinterpret_cast<const int4*>(dst)[i];
        atomicAdd(&hist[d.x], 1);
        atomicAdd(&hist[d.y], 1);
        atomicAdd(&hist[d.z], 1);
        atomicAdd(&hist[d.w], 1);
    }
}
__global__ void scan_hist(const int* __restrict__ hist, int* rowptr, int* woff, int n) {
    __shared__ int sums[1024];
    const int t = threadIdx.x;
    const int chunk = (n + 1023) / 1024;
    const int begin = t * chunk;
    const int end   = min(begin + chunk, n);
    int s = 0;
    for (int i = begin; i < end; i++) s += hist[i];
    sums[t] = s;
    __syncthreads();
    for (int d = 1; d < 1024; d <<= 1) {
        int v = (t >= d) ? sums[t - d] : 0;
        __syncthreads();
        sums[t] += v;
        __syncthreads();
    }
    int off = sums[t] - s;   // exclusive prefix
    for (int i = begin; i < end; i++) {
        rowptr[i] = off;
        woff[i]   = off;
        off += hist[i];
    }
    if (end == n && begin <= n) rowptr[n] = off;
}
__global__ void edge_bucket4(const int* __restrict__ src, const int* __restrict__ dst,
                             int* woff, int* ssrc, int E4) {
    int i = blockIdx.x * blockDim.x + threadIdx.x;
    if (i < E4) {
        int4 d = reinterpret_cast<const int4*>(dst)[i];
        int4 s = reinterpret_cast<const int4*>(src)[i];
        int p0 = atomicAdd(&woff[d.x], 1);
        int p1 = atomicAdd(&woff[d.y], 1);
        int p2 = atomicAdd(&woff[d.z], 1);
        int p3 = atomicAdd(&woff[d.w], 1);
        ssrc[p0] = s.x;
        ssrc[p1] = s.y;
        ssrc[p2] = s.z;
        ssrc[p3] = s.w;
    }
}

// ====== BIG dual GEMM (FFMA2, cp.async double-buffered, KC=16) ==============
// C0 = act(A)@W0+b0 ; C1 = act(A)@W1+b1. BN=128, TM=8, TN=4, BM=32.
// W tiles: cp.async (no staging regs). A tile: 1 float4 staged (ReLU fold).
__global__ void __launch_bounds__(256, 3)
gemm_dual_big_db(const float* __restrict__ A,
                 const float* __restrict__ W0, const float* __restrict__ b0,
                 const float* __restrict__ W1, const float* __restrict__ b1,
                 float* __restrict__ C0, float* __restrict__ C1,
                 int N, int relu_in)
{
    constexpr int BN = 128, K = 128, KC = 16;
    constexpr int TM = 8, TN = 4;
    constexpr int TCOLS = (2 * BN) / TN;     // 64
    constexpr int TROWS = 256 / TCOLS;       // 4
    constexpr int BM = TROWS * TM;           // 32
    constexpr int NCH = K / KC;              // 8 chunks

    __shared__ __align__(16) float As[2][KC][BM + 4];
    __shared__ __align__(16) float Wsm[2][KC][2 * BN];

    const int t  = threadIdx.x;
    const int tx = t % TCOLS;
    const int ty = t / TCOLS;
    const int rowBase = blockIdx.x * BM;

    unsigned long long acc2[TM / 2][TN];
    #pragma unroll
    for (int i = 0; i < TM / 2; i++)
        #pragma unroll
        for (int j = 0; j < TN; j++) acc2[i][j] = 0ull;

    // per-thread load roles (constant across chunks)
    const bool aLoader = (t < (BM * KC) / 4);          // 128 threads
    const int  ar_ = t >> 2;                            // A row 0..31
    const int  ac4 = t & 3;                             // A col-quad 0..3
    const int  agr = rowBase + ar_;

    // ---- prologue: stage chunk 0 ----
    {
        if (aLoader) {
            float4 v = make_float4(0.f, 0.f, 0.f, 0.f);
            if (agr < N) {
                v = reinterpret_cast<const float4*>(A + (size_t)agr * K)[ac4];
                if (relu_in) {
                    v.x = fmaxf(v.x, 0.f); v.y = fmaxf(v.y, 0.f);
                    v.z = fmaxf(v.z, 0.f); v.w = fmaxf(v.w, 0.f);
                }
            }
            As[0][ac4 * 4 + 0][ar_] = v.x;
            As[0][ac4 * 4 + 1][ar_] = v.y;
            As[0][ac4 * 4 + 2][ar_] = v.z;
            As[0][ac4 * 4 + 3][ar_] = v.w;
        }
        #pragma unroll
        for (int i = 0; i < 4; i++) {                  // 1024 float4 / 256 thr
            int fi = t + i * 256;
            int r  = fi >> 6;                           // / (2BN/4)
            int c4 = fi & 63;
            int col = c4 * 4;
            const float* src = (col < BN) ? (W0 + (size_t)r * BN + col)
                                          : (W1 + (size_t)r * BN + (col - BN));
            cp_async16(&Wsm[0][r][c4 * 4], src);
        }
        cp_async_commit();
        cp_async_wait_all();
        __syncthreads();
    }

    for (int c = 0; c < NCH; c++) {
        const int cur = c & 1;
        const int nxt = cur ^ 1;
        const int kcn = (c + 1) * KC;
        float4 aNext = make_float4(0.f, 0.f, 0.f, 0.f);

        // issue loads for chunk c+1 BEFORE computing chunk c
        if (c + 1 < NCH) {
            if (aLoader && agr < N) {
                aNext = reinterpret_cast<const float4*>(A + (size_t)agr * K + kcn)[ac4];
                if (relu_in) {
                    aNext.x = fmaxf(aNext.x, 0.f); aNext.y = fmaxf(aNext.y, 0.f);
                    aNext.z = fmaxf(aNext.z, 0.f); aNext.w = fmaxf(aNext.w, 0.f);
                }
            }
            #pragma unroll
            for (int i = 0; i < 4; i++) {
                int fi = t + i * 256;
                int r  = fi >> 6;
                int c4 = fi & 63;
                int col = c4 * 4;
                const float* src = (col < BN) ? (W0 + (size_t)(kcn + r) * BN + col)
                                              : (W1 + (size_t)(kcn + r) * BN + (col - BN));
                cp_async16(&Wsm[nxt][r][c4 * 4], src);
            }
            cp_async_commit();
        }

        // compute chunk c
        #pragma unroll
        for (int k = 0; k < KC; k++) {
            unsigned long long ap[TM / 2];
            #pragma unroll
            for (int i = 0; i < TM / 4; i++) {
                ulonglong2 q = *reinterpret_cast<const ulonglong2*>(&As[cur][k][ty * TM + i * 4]);
                ap[i * 2 + 0] = q.x;
                ap[i * 2 + 1] = q.y;
            }
            float4 w = *reinterpret_cast<const float4*>(&Wsm[cur][k][tx * TN]);
            unsigned long long wd[TN];
            wd[0] = pack2(w.x, w.x);
            wd[1] = pack2(w.y, w.y);
            wd[2] = pack2(w.z, w.z);
            wd[3] = pack2(w.w, w.w);
            #pragma unroll
            for (int i = 0; i < TM / 2; i++)
                #pragma unroll
                for (int j = 0; j < TN; j++)
                    acc2[i][j] = fma2(ap[i], wd[j], acc2[i][j]);
        }

        if (c + 1 < NCH) {
            if (aLoader) {
                As[nxt][ac4 * 4 + 0][ar_] = aNext.x;
                As[nxt][ac4 * 4 + 1][ar_] = aNext.y;
                As[nxt][ac4 * 4 + 2][ar_] = aNext.z;
                As[nxt][ac4 * 4 + 3][ar_] = aNext.w;
            }
            cp_async_wait_all();
            __syncthreads();
        }
    }

    const int half = (tx * TN) / BN;
    const int col  = (tx * TN) % BN;
    float*       C  = half ? C1 : C0;
    const float* bb = half ? b1 : b0;
    float4 bias4 = *reinterpret_cast<const float4*>(bb + col);
    #pragma unroll
    for (int i = 0; i < TM / 2; i++) {
        float lo[TN], hi[TN];
        #pragma unroll
        for (int j = 0; j < TN; j++) unpack2(acc2[i][j], lo[j], hi[j]);
        int gr0 = rowBase + ty * TM + 2 * i;
        int gr1 = gr0 + 1;
        if (gr0 < N) {
            float4 o = make_float4(lo[0] + bias4.x, lo[1] + bias4.y,
                                   lo[2] + bias4.z, lo[3] + bias4.w);
            *reinterpret_cast<float4*>(C + (size_t)gr0 * BN + col) = o;
        }
        if (gr1 < N) {
            float4 o = make_float4(hi[0] + bias4.x, hi[1] + bias4.y,
                                   hi[2] + bias4.z, hi[3] + bias4.w);
            *reinterpret_cast<float4*>(C + (size_t)gr1 * BN + col) = o;
        }
    }
}

// ---------------- small dual GEMM (R6 exact, single-buffered) ---------------
template<int BN, int TM, int TN, int MAXB>
__global__ void __launch_bounds__(256, MAXB)
gemm_dual_k128(const float* __restrict__ A,
               const float* __restrict__ W0, const float* __restrict__ b0,
               const float* __restrict__ W1, const float* __restrict__ b1,
               float* __restrict__ C0, float* __restrict__ C1,
               int N, int relu_in)
{
    constexpr int K = 128, KC = 32;
    constexpr int TCOLS = (2 * BN) / TN;
    constexpr int TROWS = 256 / TCOLS;
    constexpr int BM = TROWS * TM;

    __shared__ __align__(16) float As[KC][BM + 4];
    __shared__ __align__(16) float Wsm[KC][2 * BN];

    const int t  = threadIdx.x;
    const int tx = t % TCOLS;
    const int ty = t / TCOLS;
    const int rowBase = blockIdx.x * BM;

    unsigned long long acc2[TM / 2][TN];
    #pragma unroll
    for (int i = 0; i < TM / 2; i++)
        #pragma unroll
        for (int j = 0; j < TN; j++) acc2[i][j] = 0ull;

    for (int kc = 0; kc < K; kc += KC) {
        #pragma unroll
        for (int i = 0; i < (BM * KC) / (256 * 4); ++i) {
            int fi = t + i * 256;
            int r  = fi / (KC / 4);
            int c4 = fi % (KC / 4);
            int gr = rowBase + r;
            float4 v = make_float4(0.f, 0.f, 0.f, 0.f);
            if (gr < N) {
                v = reinterpret_cast<const float4*>(A + (size_t)gr * K + kc)[c4];
                if (relu_in) {
                    v.x = fmaxf(v.x, 0.f); v.y = fmaxf(v.y, 0.f);
                    v.z = fmaxf(v.z, 0.f); v.w = fmaxf(v.w, 0.f);
                }
            }
            As[c4 * 4 + 0][r] = v.x;
            As[c4 * 4 + 1][r] = v.y;
            As[c4 * 4 + 2][r] = v.z;
            As[c4 * 4 + 3][r] = v.w;
        }
        #pragma unroll
        for (int i = 0; i < (KC * 2 * BN) / (256 * 4); ++i) {
            int fi = t + i * 256;
            int r  = fi / ((2 * BN) / 4);
            int c4 = fi % ((2 * BN) / 4);
            int col = c4 * 4;
            float4 v;
            if (col < BN) v = reinterpret_cast<const float4*>(W0 + (size_t)(kc + r) * BN + col)[0];
            else          v = reinterpret_cast<const float4*>(W1 + (size_t)(kc + r) * BN + (col - BN))[0];
            reinterpret_cast<float4*>(&Wsm[r][0])[c4] = v;
        }
        __syncthreads();

        #pragma unroll
        for (int k = 0; k < KC; k++) {
            unsigned long long ap[TM / 2];
            #pragma unroll
            for (int i = 0; i < TM / 4; i++) {
                ulonglong2 q = *reinterpret_cast<const ulonglong2*>(&As[k][ty * TM + i * 4]);
                ap[i * 2 + 0] = q.x;
                ap[i * 2 + 1] = q.y;
            }
            unsigned long long wd[TN];
            #pragma unroll
            for (int j = 0; j < TN / 4; j++) {
                float4 w = *reinterpret_cast<const float4*>(&Wsm[k][tx * TN + j * 4]);
                wd[j * 4 + 0] = pack2(w.x, w.x);
                wd[j * 4 + 1] = pack2(w.y, w.y);
                wd[j * 4 + 2] = pack2(w.z, w.z);
                wd[j * 4 + 3] = pack2(w.w, w.w);
            }
            #pragma unroll
            for (int i = 0; i < TM / 2; i++)
                #pragma unroll
                for (int j = 0; j < TN; j++)
                    acc2[i][j] = fma2(ap[i], wd[j], acc2[i][j]);
        }
        __syncthreads();
    }

    const int half = (tx * TN) / BN;
    const int col  = (tx * TN) % BN;
    float*       C  = half ? C1 : C0;
    const float* bb = half ? b1 : b0;
    float bias[TN];
    #pragma unroll
    for (int j = 0; j < TN; j++) bias[j] = bb[col + j];

    #pragma unroll
    for (int i = 0; i < TM / 2; i++) {
        float lo[TN], hi[TN];
        #pragma unroll
        for (int j = 0; j < TN; j++) unpack2(acc2[i][j], lo[j], hi[j]);
        int gr0 = rowBase + ty * TM + 2 * i;
        int gr1 = gr0 + 1;
        if (gr0 < N) {
            #pragma unroll
            for (int j = 0; j < TN / 4; j++) {
                float4 o = make_float4(lo[j*4+0] + bias[j*4+0], lo[j*4+1] + bias[j*4+1],
                                       lo[j*4+2] + bias[j*4+2], lo[j*4+3] + bias[j*4+3]);
                *reinterpret_cast<float4*>(C + (size_t)gr0 * BN + col + j * 4) = o;
            }
        }
        if (gr1 < N) {
            #pragma unroll
            for (int j = 0; j < TN / 4; j++) {
                float4 o = make_float4(hi[j*4+0] + bias[j*4+0], hi[j*4+1] + bias[j*4+1],
                                       hi[j*4+2] + bias[j*4+2], hi[j*4+3] + bias[j*4+3]);
                *reinterpret_cast<float4*>(C + (size_t)gr1 * BN + col + j * 4) = o;
            }
        }
    }
}

// ========== CSR edge aggregation, H=4: warp per dst, prefetch depth 2 =======
// (exact R6 structure — best measured edge kernel; do not touch)
__global__ void edge_csr4(const int* __restrict__ rowptr, const int* __restrict__ ssrc,
                          const float* __restrict__ fs, const float* __restrict__ fd,
                          const float* __restrict__ a, float* __restrict__ out, int N)
{
    const int lane = threadIdx.x & 31;
    const int d    = (blockIdx.x * blockDim.x + threadIdx.x) >> 5;
    if (d >= N) return;

    const float4* fs4 = reinterpret_cast<const float4*>(fs);
    float4 v  = reinterpret_cast<const float4*>(fd)[(size_t)d * 32 + lane];
    float4 av = reinterpret_cast<const float4*>(a)[lane];

    float4 acc = make_float4(0.f, 0.f, 0.f, 0.f);
    float den = 0.f;

    const int start = rowptr[d];
    const int end   = rowptr[d + 1];
    if (start < end) {
        const int last = end - 1;
        int i1 = min(start + 1, last);
        float4 u0 = fs4[(size_t)__ldg(ssrc + start) * 32 + lane];
        float4 u1 = fs4[(size_t)__ldg(ssrc + i1)    * 32 + lane];
        for (int i = start; i < end; i++) {
            float4 u = u0;
            u0 = u1;
            int nx = min(i + 2, last);                 // clamped prefetch (depth 2)
            u1 = fs4[(size_t)__ldg(ssrc + nx) * 32 + lane];
            float p = lrelu(u.x + v.x) * av.x + lrelu(u.y + v.y) * av.y
                    + lrelu(u.z + v.z) * av.z + lrelu(u.w + v.w) * av.w;
            p += __shfl_xor_sync(0xffffffffu, p, 1);
            p += __shfl_xor_sync(0xffffffffu, p, 2);
            p += __shfl_xor_sync(0xffffffffu, p, 4);
            float ex = __expf(p);    // softmax shift-invariant; logits are O(1)
            acc.x = fmaf(u.x, ex, acc.x);
            acc.y = fmaf(u.y, ex, acc.y);
            acc.z = fmaf(u.z, ex, acc.z);
            acc.w = fmaf(u.w, ex, acc.w);
            den += ex;
        }
    }
    float sc = (den > 0.f) ? 1.0f / den : 0.f;   // zero-degree -> zeros
    acc.x *= sc; acc.y *= sc; acc.z *= sc; acc.w *= sc;
    reinterpret_cast<float4*>(out)[(size_t)d * 32 + lane] = acc;
}

// ========== CSR edge aggregation, H=1 (32 feats): warp=dst, 4 edge slots ====
__global__ void edge_csr1(const int* __restrict__ rowptr, const int* __restrict__ ssrc,
                          const float* __restrict__ fs, const float* __restrict__ fd,
                          const float* __restrict__ a, float* __restrict__ out, int N)
{
    const int lane = threadIdx.x & 31;
    const int d    = (blockIdx.x * blockDim.x + threadIdx.x) >> 5;
    if (d >= N) return;
    const int slot = lane >> 3;
    const int sub  = lane & 7;

    const float4* fs4 = reinterpret_cast<const float4*>(fs);
    float4 v  = reinterpret_cast<const float4*>(fd)[(size_t)d * 8 + sub];
    float4 av = reinterpret_cast<const float4*>(a)[sub];

    float4 acc = make_float4(0.f, 0.f, 0.f, 0.f);
    float den = 0.f;

    const int start = rowptr[d];
    const int end   = rowptr[d + 1];
    const int iters = (end - start + 3) >> 2;

    int idx0 = start + slot;
    float4 un = make_float4(0.f, 0.f, 0.f, 0.f);
    if (idx0 < end) un = fs4[(size_t)__ldg(ssrc + idx0) * 8 + sub];

    for (int it = 0; it < iters; it++) {
        bool ok = (start + it * 4 + slot) < end;
        float4 u = un;
        int nidx = start + (it + 1) * 4 + slot;
        if (nidx < end) un = fs4[(size_t)__ldg(ssrc + nidx) * 8 + sub];
        else            un = make_float4(0.f, 0.f, 0.f, 0.f);

        float p = lrelu(u.x + v.x) * av.x + lrelu(u.y + v.y) * av.y
                + lrelu(u.z + v.z) * av.z + lrelu(u.w + v.w) * av.w;
        p += __shfl_xor_sync(0xffffffffu, p, 1);
        p += __shfl_xor_sync(0xffffffffu, p, 2);
        p += __shfl_xor_sync(0xffffffffu, p, 4);
        float ex = ok ? __expf(p) : 0.f;
        acc.x = fmaf(u.x, ex, acc.x);
        acc.y = fmaf(u.y, ex, acc.y);
        acc.z = fmaf(u.z, ex, acc.z);
        acc.w = fmaf(u.w, ex, acc.w);
        den += ex;
    }
    #pragma unroll
    for (int m = 8; m <= 16; m <<= 1) {
        acc.x += __shfl_xor_sync(0xffffffffu, acc.x, m);
        acc.y += __shfl_xor_sync(0xffffffffu, acc.y, m);
        acc.z += __shfl_xor_sync(0xffffffffu, acc.z, m);
        acc.w += __shfl_xor_sync(0xffffffffu, acc.w, m);
        den   += __shfl_xor_sync(0xffffffffu, den,   m);
    }
    if (slot == 0) {
        float sc = (den > 0.f) ? 1.0f / den : 0.f;
        acc.x *= sc; acc.y *= sc; acc.z *= sc; acc.w *= sc;
        reinterpret_cast<float4*>(out)[(size_t)d * 8 + sub] = acc;
    }
}

// ---------------- launch -----------------------------------------------------
extern "C" void kernel_launch(void* const* d_in, const int* in_sizes, int n_in,
                              void* d_out, int out_size)
{
    const float* feat = (const float*)d_in[0];
    const int*   src  = (const int*)d_in[1];
    const int*   dst  = (const int*)d_in[2];
    const float* Ws0 = (const float*)d_in[3];  const float* bs0 = (const float*)d_in[4];
    const float* Wd0 = (const float*)d_in[5];  const float* bd0 = (const float*)d_in[6];
    const float* a0  = (const float*)d_in[7];
    const float* Ws1 = (const float*)d_in[8];  const float* bs1 = (const float*)d_in[9];
    const float* Wd1 = (const float*)d_in[10]; const float* bd1 = (const float*)d_in[11];
    const float* a1  = (const float*)d_in[12];
    const float* Ws2 = (const float*)d_in[13]; const float* bs2 = (const float*)d_in[14];
    const float* Wd2 = (const float*)d_in[15]; const float* bd2 = (const float*)d_in[16];
    const float* a2  = (const float*)d_in[17];
    float* out = (float*)d_out;

    const int N = in_sizes[0] / 128;
    const int E = in_sizes[1];

    float *fs, *fd, *h;
    int *hist, *rowptr, *woff, *ssrc;
    cudaGetSymbolAddress((void**)&fs,     g_fs);
    cudaGetSymbolAddress((void**)&fd,     g_fd);
    cudaGetSymbolAddress((void**)&h,      g_h);
    cudaGetSymbolAddress((void**)&hist,   g_hist);
    cudaGetSymbolAddress((void**)&rowptr, g_rowptr);
    cudaGetSymbolAddress((void**)&woff,   g_woff);
    cudaGetSymbolAddress((void**)&ssrc,   g_ssrc);

    const int gemmGridBig   = (N + 31) / 32;   // BM=32
    const int gemmGridSmall = (N + 63) / 64;   // BM=64
    const int edgeGrid = (N * 32 + 255) / 256; // one warp per dst
    const int E4 = E / 4;
    const int eg4 = (E4 + 255) / 256;

    // ---- CSR build (src/dst constant across layers; reused 3x) ----
    cudaMemsetAsync(hist, 0, (size_t)N * sizeof(int));
    hist_count4<<<eg4, 256>>>(dst, hist, E4);
    scan_hist<<<1, 1024>>>(hist, rowptr, woff, N);
    edge_bucket4<<<eg4, 256>>>(src, dst, woff, ssrc, E4);

    // ---- layer 0 (input 128 -> 4x32) ----
    gemm_dual_big_db<<<gemmGridBig, 256>>>(feat, Ws0, bs0, Wd0, bd0, fs, fd, N, 0);
    edge_csr4<<<edgeGrid, 256>>>(rowptr, ssrc, fs, fd, a0, h, N);

    // ---- layer 1 (ReLU(h) 128 -> 4x32) ----
    gemm_dual_big_db<<<gemmGridBig, 256>>>(h, Ws1, bs1, Wd1, bd1, fs, fd, N, 1);
    edge_csr4<<<edgeGrid, 256>>>(rowptr, ssrc, fs, fd, a1, h, N);

    // ---- layer 2 (ReLU(h) 128 -> 1x32), mean over 1 head == identity ----
    gemm_dual_k128<32, 4, 4, 2><<<gemmGridSmall, 256>>>(h, Ws2, bs2, Wd2, bd2, fs, fd, N, 1);
    edge_csr1<<<edgeGrid, 256>>>(rowptr, ssrc, fs, fd, a2, out, N);
}

// round 15
// speedup vs baseline: 1.2406x; 1.1494x over previous
#include <cuda_runtime.h>
#include <cstdint>

#define NNODES 50000
#define NEDGES 800000

// ---------------- scratch (device globals; no allocation allowed) ----------
__device__ float g_fs[NNODES * 128];
__device__ float g_fd[NNODES * 128];
__device__ float g_h [NNODES * 128];
__device__ int   g_hist[NNODES];
__device__ int   g_rowptr[NNODES + 1];
__device__ int   g_woff[NNODES];
__device__ int   g_ssrc[NEDGES];

__device__ __forceinline__ float lrelu(float x) { return x > 0.f ? x : 0.2f * x; }

// ---- packed f32x2 helpers (FFMA2, small GEMM only) -------------------------
__device__ __forceinline__ unsigned long long pack2(float lo, float hi) {
    unsigned long long r;
    asm("mov.b64 %0, {%1, %2};" : "=l"(r) : "f"(lo), "f"(hi));
    return r;
}
__device__ __forceinline__ void unpack2(unsigned long long v, float& lo, float& hi) {
    asm("mov.b64 {%0, %1}, %2;" : "=f"(lo), "=f"(hi) : "l"(v));
}
__device__ __forceinline__ unsigned long long fma2(unsigned long long a,
                                                   unsigned long long b,
                                                   unsigned long long c) {
    unsigned long long d;
    asm("fma.rn.f32x2 %0, %1, %2, %3;" : "=l"(d) : "l"(a), "l"(b), "l"(c));
    return d;
}

// ---- bf16 helpers ----------------------------------------------------------
__device__ __forceinline__ uint32_t bf16_bits_rn(float x) {   // bf16 in high 16
    uint32_t u = __float_as_uint(x);
    return (u + 0x7fffu + ((u >> 16) & 1u)) & 0xffff0000u;
}
// pack {lo16 = even element, hi16 = odd element}
__device__ __forceinline__ uint32_t bf16pack(uint32_t bits_even, uint32_t bits_odd) {
    return bits_odd | (bits_even >> 16);
}
__device__ __forceinline__ void mma_bf16(float& d0, float& d1, float& d2, float& d3,
                                         uint32_t a0, uint32_t a1, uint32_t a2, uint32_t a3,
                                         uint32_t b0, uint32_t b1) {
    asm volatile("mma.sync.aligned.m16n8k16.row.col.f32.bf16.bf16.f32 "
                 "{%0,%1,%2,%3}, {%4,%5,%6,%7}, {%8,%9}, {%0,%1,%2,%3};"
                 : "+f"(d0), "+f"(d1), "+f"(d2), "+f"(d3)
                 : "r"(a0), "r"(a1), "r"(a2), "r"(a3), "r"(b0), "r"(b1));
}

// ================= CSR construction (once per launch, reused 3x) ============
__global__ void hist_count4(const int* __restrict__ dst, int* hist, int E4) {
    int i = blockIdx.x * blockDim.x + threadIdx.x;
    if (i < E4) {
        int4 d = reinterpret_cast<const int4*>(dst)[i];
        atomicAdd(&hist[d.x], 1);
        atomicAdd(&hist[d.y], 1);
        atomicAdd(&hist[d.z], 1);
        atomicAdd(&hist[d.w], 1);
    }
}
__global__ void scan_hist(const int* __restrict__ hist, int* rowptr, int* woff, int n) {
    __shared__ int sums[1024];
    const int t = threadIdx.x;
    const int chunk = (n + 1023) / 1024;
    const int begin = t * chunk;
    const int end   = min(begin + chunk, n);
    int s = 0;
    for (int i = begin; i < end; i++) s += hist[i];
    sums[t] = s;
    __syncthreads();
    for (int d = 1; d < 1024; d <<= 1) {
        int v = (t >= d) ? sums[t - d] : 0;
        __syncthreads();
        sums[t] += v;
        __syncthreads();
    }
    int off = sums[t] - s;   // exclusive prefix
    for (int i = begin; i < end; i++) {
        rowptr[i] = off;
        woff[i]   = off;
        off += hist[i];
    }
    if (end == n && begin <= n) rowptr[n] = off;
}
__global__ void edge_bucket4(const int* __restrict__ src, const int* __restrict__ dst,
                             int* woff, int* ssrc, int E4) {
    int i = blockIdx.x * blockDim.x + threadIdx.x;
    if (i < E4) {
        int4 d = reinterpret_cast<const int4*>(dst)[i];
        int4 s = reinterpret_cast<const int4*>(src)[i];
        int p0 = atomicAdd(&woff[d.x], 1);
        int p1 = atomicAdd(&woff[d.y], 1);
        int p2 = atomicAdd(&woff[d.z], 1);
        int p3 = atomicAdd(&woff[d.w], 1);
        ssrc[p0] = s.x;
        ssrc[p1] = s.y;
        ssrc[p2] = s.z;
        ssrc[p3] = s.w;
    }
}

// ====== BIG dual GEMM via tensor cores (bf16 mma.sync, 3-term split) ========
// C0 = act(A)@W0+b0 ; C1 = act(A)@W1+b1, A [N,128], W [128,128] each.
// Error-compensated: X = X_hi(bf16) + X_lo(bf16); C ≈ Ah·Wh + Al·Wh + Ah·Wl.
// BM=64 rows/block, 8 warps: warp>>1 = row-group (16 rows), warp&1 = C0/C1.
__global__ void __launch_bounds__(256, 2)
gemm_dual_mma(const float* __restrict__ A,
              const float* __restrict__ W0, const float* __restrict__ b0,
              const float* __restrict__ W1, const float* __restrict__ b1,
              float* __restrict__ C0, float* __restrict__ C1,
              int N, int relu_in)
{
    constexpr int K = 128, KC = 16, NCH = K / KC;   // 8 chunks, 1 mma-kstep each
    // A pairs (bf16x2 along k): [64 rows][KC/2=8 -> pad 12]  (banks verified)
    __shared__ uint32_t Ap_hi[64][12], Ap_lo[64][12];
    // W pairs: [KC/2=8][256 cols -> pad 264]                  (banks verified)
    __shared__ uint32_t Wp_hi[8][264], Wp_lo[8][264];

    const int t    = threadIdx.x;
    const int lane = t & 31;
    const int warp = t >> 5;
    const int wm   = warp >> 1;          // 0..3 row group (16 rows)
    const int wn   = warp & 1;           // 0 -> C0, 1 -> C1
    const int rowBase = blockIdx.x * 64;

    float c[16][4];                      // 16 ntiles x (2x2) f32
    #pragma unroll
    for (int i = 0; i < 16; i++)
        #pragma unroll
        for (int j = 0; j < 4; j++) c[i][j] = 0.f;

    const int arow = t >> 2;             // A-loader: row 0..63
    const int akk  = t & 3;              // handles kk pairs {akk, akk+4}

    for (int ch = 0; ch < NCH; ch++) {
        const int kc = ch * KC;
        // ---- stage A tile: 64 x 16 fp32 -> bf16x2 hi/lo pairs --------------
        {
            int gr = rowBase + arow;
            #pragma unroll
            for (int q = 0; q < 2; q++) {          // kk = akk and akk+4
                int kk = akk + q * 4;
                float2 v = make_float2(0.f, 0.f);
                if (gr < N)
                    v = *reinterpret_cast<const float2*>(A + (size_t)gr * K + kc + 2 * kk);
                if (relu_in) { v.x = fmaxf(v.x, 0.f); v.y = fmaxf(v.y, 0.f); }
                uint32_t hx = bf16_bits_rn(v.x), hy = bf16_bits_rn(v.y);
                float rx = v.x - __uint_as_float(hx);
                float ry = v.y - __uint_as_float(hy);
                Ap_hi[arow][kk] = bf16pack(hx, hy);
                Ap_lo[arow][kk] = bf16pack(bf16_bits_rn(rx), bf16_bits_rn(ry));
            }
        }
        // ---- stage W tile: 16 x 256 fp32 -> bf16x2 (pairs along k) ---------
        #pragma unroll
        for (int i = 0; i < 8; i++) {
            int kk = i;                 // k-pair index; rows kc+2kk, kc+2kk+1
            int n  = t;                 // 0..255
            const float* Wbase = (n < 128) ? W0 : W1;
            int nn = n & 127;
            float w0 = Wbase[(size_t)(kc + 2 * kk)     * 128 + nn];
            float w1 = Wbase[(size_t)(kc + 2 * kk + 1) * 128 + nn];
            uint32_t h0 = bf16_bits_rn(w0), h1 = bf16_bits_rn(w1);
            float r0 = w0 - __uint_as_float(h0);
            float r1 = w1 - __uint_as_float(h1);
            Wp_hi[kk][n] = bf16pack(h0, h1);
            Wp_lo[kk][n] = bf16pack(bf16_bits_rn(r0), bf16_bits_rn(r1));
        }
        __syncthreads();

        // ---- one m16n8k16 k-step per chunk ---------------------------------
        const int frow = wm * 16 + (lane >> 2);
        const int fkk  = lane & 3;
        uint32_t ah0 = Ap_hi[frow    ][fkk    ];
        uint32_t ah1 = Ap_hi[frow + 8][fkk    ];
        uint32_t ah2 = Ap_hi[frow    ][fkk + 4];
        uint32_t ah3 = Ap_hi[frow + 8][fkk + 4];
        uint32_t al0 = Ap_lo[frow    ][fkk    ];
        uint32_t al1 = Ap_lo[frow + 8][fkk    ];
        uint32_t al2 = Ap_lo[frow    ][fkk + 4];
        uint32_t al3 = Ap_lo[frow + 8][fkk + 4];

        const int nlane = wn * 128 + (lane >> 2);
        #pragma unroll
        for (int nt = 0; nt < 16; nt++) {
            int n = nlane + nt * 8;
            uint32_t bh0 = Wp_hi[fkk    ][n];
            uint32_t bh1 = Wp_hi[fkk + 4][n];
            uint32_t bl0 = Wp_lo[fkk    ][n];
            uint32_t bl1 = Wp_lo[fkk + 4][n];
            mma_bf16(c[nt][0], c[nt][1], c[nt][2], c[nt][3],
                     ah0, ah1, ah2, ah3, bh0, bh1);
            mma_bf16(c[nt][0], c[nt][1], c[nt][2], c[nt][3],
                     al0, al1, al2, al3, bh0, bh1);
            mma_bf16(c[nt][0], c[nt][1], c[nt][2], c[nt][3],
                     ah0, ah1, ah2, ah3, bl0, bl1);
        }
        __syncthreads();
    }

    // ---- epilogue: bias + store ---------------------------------------------
    float*       C  = wn ? C1 : C0;
    const float* bb = wn ? b1 : b0;
    const int r0 = rowBase + wm * 16 + (lane >> 2);
    const int r1 = r0 + 8;
    #pragma unroll
    for (int nt = 0; nt < 16; nt++) {
        int colc = nt * 8 + 2 * (lane & 3);
        float bx = bb[colc], by = bb[colc + 1];
        if (r0 < N) {
            float2 o = make_float2(c[nt][0] + bx, c[nt][1] + by);
            *reinterpret_cast<float2*>(C + (size_t)r0 * 128 + colc) = o;
        }
        if (r1 < N) {
            float2 o = make_float2(c[nt][2] + bx, c[nt][3] + by);
            *reinterpret_cast<float2*>(C + (size_t)r1 * 128 + colc) = o;
        }
    }
}

// ---------------- small dual GEMM (FFMA2, R6 exact) --------------------------
template<int BN, int TM, int TN, int MAXB>
__global__ void __launch_bounds__(256, MAXB)
gemm_dual_k128(const float* __restrict__ A,
               const float* __restrict__ W0, const float* __restrict__ b0,
               const float* __restrict__ W1, const float* __restrict__ b1,
               float* __restrict__ C0, float* __restrict__ C1,
               int N, int relu_in)
{
    constexpr int K = 128, KC = 32;
    constexpr int TCOLS = (2 * BN) / TN;
    constexpr int TROWS = 256 / TCOLS;
    constexpr int BM = TROWS * TM;

    __shared__ __align__(16) float As[KC][BM + 4];
    __shared__ __align__(16) float Wsm[KC][2 * BN];

    const int t  = threadIdx.x;
    const int tx = t % TCOLS;
    const int ty = t / TCOLS;
    const int rowBase = blockIdx.x * BM;

    unsigned long long acc2[TM / 2][TN];
    #pragma unroll
    for (int i = 0; i < TM / 2; i++)
        #pragma unroll
        for (int j = 0; j < TN; j++) acc2[i][j] = 0ull;

    for (int kc = 0; kc < K; kc += KC) {
        #pragma unroll
        for (int i = 0; i < (BM * KC) / (256 * 4); ++i) {
            int fi = t + i * 256;
            int r  = fi / (KC / 4);
            int c4 = fi % (KC / 4);
            int gr = rowBase + r;
            float4 v = make_float4(0.f, 0.f, 0.f, 0.f);
            if (gr < N) {
                v = reinterpret_cast<const float4*>(A + (size_t)gr * K + kc)[c4];
                if (relu_in) {
                    v.x = fmaxf(v.x, 0.f); v.y = fmaxf(v.y, 0.f);
                    v.z = fmaxf(v.z, 0.f); v.w = fmaxf(v.w, 0.f);
                }
            }
            As[c4 * 4 + 0][r] = v.x;
            As[c4 * 4 + 1][r] = v.y;
            As[c4 * 4 + 2][r] = v.z;
            As[c4 * 4 + 3][r] = v.w;
        }
        #pragma unroll
        for (int i = 0; i < (KC * 2 * BN) / (256 * 4); ++i) {
            int fi = t + i * 256;
            int r  = fi / ((2 * BN) / 4);
            int c4 = fi % ((2 * BN) / 4);
            int col = c4 * 4;
            float4 v;
            if (col < BN) v = reinterpret_cast<const float4*>(W0 + (size_t)(kc + r) * BN + col)[0];
            else          v = reinterpret_cast<const float4*>(W1 + (size_t)(kc + r) * BN + (col - BN))[0];
            reinterpret_cast<float4*>(&Wsm[r][0])[c4] = v;
        }
        __syncthreads();

        #pragma unroll
        for (int k = 0; k < KC; k++) {
            unsigned long long ap[TM / 2];
            #pragma unroll
            for (int i = 0; i < TM / 4; i++) {
                ulonglong2 q = *reinterpret_cast<const ulonglong2*>(&As[k][ty * TM + i * 4]);
                ap[i * 2 + 0] = q.x;
                ap[i * 2 + 1] = q.y;
            }
            unsigned long long wd[TN];
            #pragma unroll
            for (int j = 0; j < TN / 4; j++) {
                float4 w = *reinterpret_cast<const float4*>(&Wsm[k][tx * TN + j * 4]);
                wd[j * 4 + 0] = pack2(w.x, w.x);
                wd[j * 4 + 1] = pack2(w.y, w.y);
                wd[j * 4 + 2] = pack2(w.z, w.z);
                wd[j * 4 + 3] = pack2(w.w, w.w);
            }
            #pragma unroll
            for (int i = 0; i < TM / 2; i++)
                #pragma unroll
                for (int j = 0; j < TN; j++)
                    acc2[i][j] = fma2(ap[i], wd[j], acc2[i][j]);
        }
        __syncthreads();
    }

    const int half = (tx * TN) / BN;
    const int col  = (tx * TN) % BN;
    float*       C  = half ? C1 : C0;
    const float* bb = half ? b1 : b0;
    float bias[TN];
    #pragma unroll
    for (int j = 0; j < TN; j++) bias[j] = bb[col + j];

    #pragma unroll
    for (int i = 0; i < TM / 2; i++) {
        float lo[TN], hi[TN];
        #pragma unroll
        for (int j = 0; j < TN; j++) unpack2(acc2[i][j], lo[j], hi[j]);
        int gr0 = rowBase + ty * TM + 2 * i;
        int gr1 = gr0 + 1;
        if (gr0 < N) {
            #pragma unroll
            for (int j = 0; j < TN / 4; j++) {
                float4 o = make_float4(lo[j*4+0] + bias[j*4+0], lo[j*4+1] + bias[j*4+1],
                                       lo[j*4+2] + bias[j*4+2], lo[j*4+3] + bias[j*4+3]);
                *reinterpret_cast<float4*>(C + (size_t)gr0 * BN + col + j * 4) = o;
            }
        }
        if (gr1 < N) {
            #pragma unroll
            for (int j = 0; j < TN / 4; j++) {
                float4 o = make_float4(hi[j*4+0] + bias[j*4+0], hi[j*4+1] + bias[j*4+1],
                                       hi[j*4+2] + bias[j*4+2], hi[j*4+3] + bias[j*4+3]);
                *reinterpret_cast<float4*>(C + (size_t)gr1 * BN + col + j * 4) = o;
            }
        }
    }
}

// ========== CSR edge aggregation, H=4: warp per dst, prefetch depth 2 =======
// (exact champion structure — do not touch)
__global__ void edge_csr4(const int* __restrict__ rowptr, const int* __restrict__ ssrc,
                          const float* __restrict__ fs, const float* __restrict__ fd,
                          const float* __restrict__ a, float* __restrict__ out, int N)
{
    const int lane = threadIdx.x & 31;
    const int d    = (blockIdx.x * blockDim.x + threadIdx.x) >> 5;
    if (d >= N) return;

    const float4* fs4 = reinterpret_cast<const float4*>(fs);
    float4 v  = reinterpret_cast<const float4*>(fd)[(size_t)d * 32 + lane];
    float4 av = reinterpret_cast<const float4*>(a)[lane];

    float4 acc = make_float4(0.f, 0.f, 0.f, 0.f);
    float den = 0.f;

    const int start = rowptr[d];
    const int end   = rowptr[d + 1];
    if (start < end) {
        const int last = end - 1;
        int i1 = min(start + 1, last);
        float4 u0 = fs4[(size_t)__ldg(ssrc + start) * 32 + lane];
        float4 u1 = fs4[(size_t)__ldg(ssrc + i1)    * 32 + lane];
        for (int i = start; i < end; i++) {
            float4 u = u0;
            u0 = u1;
            int nx = min(i + 2, last);                 // clamped prefetch (depth 2)
            u1 = fs4[(size_t)__ldg(ssrc + nx) * 32 + lane];
            float p = lrelu(u.x + v.x) * av.x + lrelu(u.y + v.y) * av.y
                    + lrelu(u.z + v.z) * av.z + lrelu(u.w + v.w) * av.w;
            p += __shfl_xor_sync(0xffffffffu, p, 1);
            p += __shfl_xor_sync(0xffffffffu, p, 2);
            p += __shfl_xor_sync(0xffffffffu, p, 4);
            float ex = __expf(p);    // softmax shift-invariant; logits are O(1)
            acc.x = fmaf(u.x, ex, acc.x);
            acc.y = fmaf(u.y, ex, acc.y);
            acc.z = fmaf(u.z, ex, acc.z);
            acc.w = fmaf(u.w, ex, acc.w);
            den += ex;
        }
    }
    float sc = (den > 0.f) ? 1.0f / den : 0.f;   // zero-degree -> zeros
    acc.x *= sc; acc.y *= sc; acc.z *= sc; acc.w *= sc;
    reinterpret_cast<float4*>(out)[(size_t)d * 32 + lane] = acc;
}

// ========== CSR edge aggregation, H=1 (32 feats): warp=dst, 4 edge slots ====
__global__ void edge_csr1(const int* __restrict__ rowptr, const int* __restrict__ ssrc,
                          const float* __restrict__ fs, const float* __restrict__ fd,
                          const float* __restrict__ a, float* __restrict__ out, int N)
{
    const int lane = threadIdx.x & 31;
    const int d    = (blockIdx.x * blockDim.x + threadIdx.x) >> 5;
    if (d >= N) return;
    const int slot = lane >> 3;
    const int sub  = lane & 7;

    const float4* fs4 = reinterpret_cast<const float4*>(fs);
    float4 v  = reinterpret_cast<const float4*>(fd)[(size_t)d * 8 + sub];
    float4 av = reinterpret_cast<const float4*>(a)[sub];

    float4 acc = make_float4(0.f, 0.f, 0.f, 0.f);
    float den = 0.f;

    const int start = rowptr[d];
    const int end   = rowptr[d + 1];
    const int iters = (end - start + 3) >> 2;

    int idx0 = start + slot;
    float4 un = make_float4(0.f, 0.f, 0.f, 0.f);
    if (idx0 < end) un = fs4[(size_t)__ldg(ssrc + idx0) * 8 + sub];

    for (int it = 0; it < iters; it++) {
        bool ok = (start + it * 4 + slot) < end;
        float4 u = un;
        int nidx = start + (it + 1) * 4 + slot;
        if (nidx < end) un = fs4[(size_t)__ldg(ssrc + nidx) * 8 + sub];
        else            un = make_float4(0.f, 0.f, 0.f, 0.f);

        float p = lrelu(u.x + v.x) * av.x + lrelu(u.y + v.y) * av.y
                + lrelu(u.z + v.z) * av.z + lrelu(u.w + v.w) * av.w;
        p += __shfl_xor_sync(0xffffffffu, p, 1);
        p += __shfl_xor_sync(0xffffffffu, p, 2);
        p += __shfl_xor_sync(0xffffffffu, p, 4);
        float ex = ok ? __expf(p) : 0.f;
        acc.x = fmaf(u.x, ex, acc.x);
        acc.y = fmaf(u.y, ex, acc.y);
        acc.z = fmaf(u.z, ex, acc.z);
        acc.w = fmaf(u.w, ex, acc.w);
        den += ex;
    }
    #pragma unroll
    for (int m = 8; m <= 16; m <<= 1) {
        acc.x += __shfl_xor_sync(0xffffffffu, acc.x, m);
        acc.y += __shfl_xor_sync(0xffffffffu, acc.y, m);
        acc.z += __shfl_xor_sync(0xffffffffu, acc.z, m);
        acc.w += __shfl_xor_sync(0xffffffffu, acc.w, m);
        den   += __shfl_xor_sync(0xffffffffu, den,   m);
    }
    if (slot == 0) {
        float sc = (den > 0.f) ? 1.0f / den : 0.f;
        acc.x *= sc; acc.y *= sc; acc.z *= sc; acc.w *= sc;
        reinterpret_cast<float4*>(out)[(size_t)d * 8 + sub] = acc;
    }
}

// ---------------- launch -----------------------------------------------------
extern "C" void kernel_launch(void* const* d_in, const int* in_sizes, int n_in,
                              void* d_out, int out_size)
{
    const float* feat = (const float*)d_in[0];
    const int*   src  = (const int*)d_in[1];
    const int*   dst  = (const int*)d_in[2];
    const float* Ws0 = (const float*)d_in[3];  const float* bs0 = (const float*)d_in[4];
    const float* Wd0 = (const float*)d_in[5];  const float* bd0 = (const float*)d_in[6];
    const float* a0  = (const float*)d_in[7];
    const float* Ws1 = (const float*)d_in[8];  const float* bs1 = (const float*)d_in[9];
    const float* Wd1 = (const float*)d_in[10]; const float* bd1 = (const float*)d_in[11];
    const float* a1  = (const float*)d_in[12];
    const float* Ws2 = (const float*)d_in[13]; const float* bs2 = (const float*)d_in[14];
    const float* Wd2 = (const float*)d_in[15]; const float* bd2 = (const float*)d_in[16];
    const float* a2  = (const float*)d_in[17];
    float* out = (float*)d_out;

    const int N = in_sizes[0] / 128;
    const int E = in_sizes[1];

    float *fs, *fd, *h;
    int *hist, *rowptr, *woff, *ssrc;
    cudaGetSymbolAddress((void**)&fs,     g_fs);
    cudaGetSymbolAddress((void**)&fd,     g_fd);
    cudaGetSymbolAddress((void**)&h,      g_h);
    cudaGetSymbolAddress((void**)&hist,   g_hist);
    cudaGetSymbolAddress((void**)&rowptr, g_rowptr);
    cudaGetSymbolAddress((void**)&woff,   g_woff);
    cudaGetSymbolAddress((void**)&ssrc,   g_ssrc);

    const int gemmGridBig   = (N + 63) / 64;   // BM=64, mma kernel
    const int gemmGridSmall = (N + 63) / 64;   // BM=64 (TM=4, TN=4)
    const int edgeGrid = (N * 32 + 255) / 256; // one warp per dst
    const int E4 = E / 4;
    const int eg4 = (E4 + 255) / 256;

    // ---- CSR build (src/dst constant across layers; reused 3x) ----
    cudaMemsetAsync(hist, 0, (size_t)N * sizeof(int));
    hist_count4<<<eg4, 256>>>(dst, hist, E4);
    scan_hist<<<1, 1024>>>(hist, rowptr, woff, N);
    edge_bucket4<<<eg4, 256>>>(src, dst, woff, ssrc, E4);

    // ---- layer 0 (input 128 -> 4x32) ----
    gemm_dual_mma<<<gemmGridBig, 256>>>(feat, Ws0, bs0, Wd0, bd0, fs, fd, N, 0);
    edge_csr4<<<edgeGrid, 256>>>(rowptr, ssrc, fs, fd, a0, h, N);

    // ---- layer 1 (ReLU(h) 128 -> 4x32) ----
    gemm_dual_mma<<<gemmGridBig, 256>>>(h, Ws1, bs1, Wd1, bd1, fs, fd, N, 1);
    edge_csr4<<<edgeGrid, 256>>>(rowptr, ssrc, fs, fd, a1, h, N);

    // ---- layer 2 (ReLU(h) 128 -> 1x32), mean over 1 head == identity ----
    gemm_dual_k128<32, 4, 4, 2><<<gemmGridSmall, 256>>>(h, Ws2, bs2, Wd2, bd2, fs, fd, N, 1);
    edge_csr1<<<edgeGrid, 256>>>(rowptr, ssrc, fs, fd, a2, out, N);
}

// round 16
// speedup vs baseline: 1.2609x; 1.0164x over previous
#include <cuda_runtime.h>
#include <cstdint>

#define NNODES 50000
#define NEDGES 800000

// ---------------- scratch (device globals; no allocation allowed) ----------
__device__ float g_fs[NNODES * 128];
__device__ float g_fd[NNODES * 128];
__device__ float g_h [NNODES * 128];
__device__ int   g_hist[NNODES];
__device__ int   g_rowptr[NNODES + 1];
__device__ int   g_woff[NNODES];
__device__ int   g_ssrc[NEDGES];
// preconverted W (bf16x2 hi/lo, [kpair][256] layout), layers 0 and 1
__device__ uint32_t g_wh0[64 * 256];
__device__ uint32_t g_wl0[64 * 256];
__device__ uint32_t g_wh1[64 * 256];
__device__ uint32_t g_wl1[64 * 256];

__device__ __forceinline__ float lrelu(float x) { return x > 0.f ? x : 0.2f * x; }

// ---- packed f32x2 helpers (FFMA2, small GEMM only) -------------------------
__device__ __forceinline__ unsigned long long pack2(float lo, float hi) {
    unsigned long long r;
    asm("mov.b64 %0, {%1, %2};" : "=l"(r) : "f"(lo), "f"(hi));
    return r;
}
__device__ __forceinline__ void unpack2(unsigned long long v, float& lo, float& hi) {
    asm("mov.b64 {%0, %1}, %2;" : "=f"(lo), "=f"(hi) : "l"(v));
}
__device__ __forceinline__ unsigned long long fma2(unsigned long long a,
                                                   unsigned long long b,
                                                   unsigned long long c) {
    unsigned long long d;
    asm("fma.rn.f32x2 %0, %1, %2, %3;" : "=l"(d) : "l"(a), "l"(b), "l"(c));
    return d;
}

// ---- bf16 helpers ----------------------------------------------------------
__device__ __forceinline__ uint32_t bf16_bits_rn(float x) {   // bf16 in high 16
    uint32_t u = __float_as_uint(x);
    return (u + 0x7fffu + ((u >> 16) & 1u)) & 0xffff0000u;
}
__device__ __forceinline__ uint32_t bf16pack(uint32_t bits_even, uint32_t bits_odd) {
    return bits_odd | (bits_even >> 16);
}
__device__ __forceinline__ void mma_bf16(float& d0, float& d1, float& d2, float& d3,
                                         uint32_t a0, uint32_t a1, uint32_t a2, uint32_t a3,
                                         uint32_t b0, uint32_t b1) {
    asm volatile("mma.sync.aligned.m16n8k16.row.col.f32.bf16.bf16.f32 "
                 "{%0,%1,%2,%3}, {%4,%5,%6,%7}, {%8,%9}, {%0,%1,%2,%3};"
                 : "+f"(d0), "+f"(d1), "+f"(d2), "+f"(d3)
                 : "r"(a0), "r"(a1), "r"(a2), "r"(a3), "r"(b0), "r"(b1));
}

// ---- W preconversion: fp32 [128,128]x2 -> packed bf16x2 hi/lo [64][256] ----
__global__ void conv_w(const float* __restrict__ W0, const float* __restrict__ W1,
                       uint32_t* __restrict__ wh, uint32_t* __restrict__ wl)
{
    int idx = blockIdx.x * 256 + threadIdx.x;   // 16384 total
    int kp  = idx >> 8;       // k-pair 0..63
    int n   = idx & 255;
    const float* Wb = (n < 128) ? W0 : W1;
    int nn = n & 127;
    float w0 = Wb[(size_t)(2 * kp)     * 128 + nn];
    float w1 = Wb[(size_t)(2 * kp + 1) * 128 + nn];
    uint32_t h0 = bf16_bits_rn(w0), h1 = bf16_bits_rn(w1);
    float r0 = w0 - __uint_as_float(h0);
    float r1 = w1 - __uint_as_float(h1);
    wh[idx] = bf16pack(h0, h1);
    wl[idx] = bf16pack(bf16_bits_rn(r0), bf16_bits_rn(r1));
}

// ================= CSR construction (once per launch, reused 3x) ============
__global__ void hist_count4(const int* __restrict__ dst, int* hist, int E4) {
    int i = blockIdx.x * blockDim.x + threadIdx.x;
    if (i < E4) {
        int4 d = reinterpret_cast<const int4*>(dst)[i];
        atomicAdd(&hist[d.x], 1);
        atomicAdd(&hist[d.y], 1);
        atomicAdd(&hist[d.z], 1);
        atomicAdd(&hist[d.w], 1);
    }
}
__global__ void scan_hist(const int* __restrict__ hist, int* rowptr, int* woff, int n) {
    __shared__ int sums[1024];
    const int t = threadIdx.x;
    const int chunk = (n + 1023) / 1024;
    const int begin = t * chunk;
    const int end   = min(begin + chunk, n);
    int s = 0;
    for (int i = begin; i < end; i++) s += hist[i];
    sums[t] = s;
    __syncthreads();
    for (int d = 1; d < 1024; d <<= 1) {
        int v = (t >= d) ? sums[t - d] : 0;
        __syncthreads();
        sums[t] += v;
        __syncthreads();
    }
    int off = sums[t] - s;   // exclusive prefix
    for (int i = begin; i < end; i++) {
        rowptr[i] = off;
        woff[i]   = off;
        off += hist[i];
    }
    if (end == n && begin <= n) rowptr[n] = off;
}
__global__ void edge_bucket4(const int* __restrict__ src, const int* __restrict__ dst,
                             int* woff, int* ssrc, int E4) {
    int i = blockIdx.x * blockDim.x + threadIdx.x;
    if (i < E4) {
        int4 d = reinterpret_cast<const int4*>(dst)[i];
        int4 s = reinterpret_cast<const int4*>(src)[i];
        int p0 = atomicAdd(&woff[d.x], 1);
        int p1 = atomicAdd(&woff[d.y], 1);
        int p2 = atomicAdd(&woff[d.z], 1);
        int p3 = atomicAdd(&woff[d.w], 1);
        ssrc[p0] = s.x;
        ssrc[p1] = s.y;
        ssrc[p2] = s.z;
        ssrc[p3] = s.w;
    }
}

// ====== BIG dual GEMM via tensor cores (bf16 mma.sync, 3-term split) ========
// W comes PRECONVERTED (g_wh/g_wl) — only A is split per-block.
__global__ void __launch_bounds__(256, 2)
gemm_dual_mma(const float* __restrict__ A,
              const uint32_t* __restrict__ wh, const uint32_t* __restrict__ wl,
              const float* __restrict__ b0, const float* __restrict__ b1,
              float* __restrict__ C0, float* __restrict__ C1,
              int N, int relu_in)
{
    constexpr int K = 128, KC = 16, NCH = K / KC;   // 8 chunks
    __shared__ uint32_t Ap_hi[64][12], Ap_lo[64][12];
    __shared__ uint32_t Wp_hi[8][264], Wp_lo[8][264];

    const int t    = threadIdx.x;
    const int lane = t & 31;
    const int warp = t >> 5;
    const int wm   = warp >> 1;          // 0..3 row group (16 rows)
    const int wn   = warp & 1;           // 0 -> C0, 1 -> C1
    const int rowBase = blockIdx.x * 64;

    float c[16][4];
    #pragma unroll
    for (int i = 0; i < 16; i++)
        #pragma unroll
        for (int j = 0; j < 4; j++) c[i][j] = 0.f;

    const int arow = t >> 2;             // A-loader: row 0..63
    const int akk  = t & 3;

    for (int ch = 0; ch < NCH; ch++) {
        const int kc = ch * KC;
        // ---- stage A tile: 64 x 16 fp32 -> bf16x2 hi/lo pairs --------------
        {
            int gr = rowBase + arow;
            #pragma unroll
            for (int q = 0; q < 2; q++) {
                int kk = akk + q * 4;
                float2 v = make_float2(0.f, 0.f);
                if (gr < N)
                    v = *reinterpret_cast<const float2*>(A + (size_t)gr * K + kc + 2 * kk);
                if (relu_in) { v.x = fmaxf(v.x, 0.f); v.y = fmaxf(v.y, 0.f); }
                uint32_t hx = bf16_bits_rn(v.x), hy = bf16_bits_rn(v.y);
                float rx = v.x - __uint_as_float(hx);
                float ry = v.y - __uint_as_float(hy);
                Ap_hi[arow][kk] = bf16pack(hx, hy);
                Ap_lo[arow][kk] = bf16pack(bf16_bits_rn(rx), bf16_bits_rn(ry));
            }
        }
        // ---- stage W tile: plain coalesced u32 copies (preconverted) -------
        {
            const uint32_t* whc = wh + (size_t)ch * 8 * 256;
            const uint32_t* wlc = wl + (size_t)ch * 8 * 256;
            #pragma unroll
            for (int i = 0; i < 8; i++) {
                int fi = t + i * 256;     // 2048 words
                int kk = fi >> 8;
                int n  = fi & 255;
                Wp_hi[kk][n] = whc[fi];
                Wp_lo[kk][n] = wlc[fi];
            }
        }
        __syncthreads();

        // ---- one m16n8k16 k-step per chunk ---------------------------------
        const int frow = wm * 16 + (lane >> 2);
        const int fkk  = lane & 3;
        uint32_t ah0 = Ap_hi[frow    ][fkk    ];
        uint32_t ah1 = Ap_hi[frow + 8][fkk    ];
        uint32_t ah2 = Ap_hi[frow    ][fkk + 4];
        uint32_t ah3 = Ap_hi[frow + 8][fkk + 4];
        uint32_t al0 = Ap_lo[frow    ][fkk    ];
        uint32_t al1 = Ap_lo[frow + 8][fkk    ];
        uint32_t al2 = Ap_lo[frow    ][fkk + 4];
        uint32_t al3 = Ap_lo[frow + 8][fkk + 4];

        const int nlane = wn * 128 + (lane >> 2);
        #pragma unroll
        for (int nt = 0; nt < 16; nt++) {
            int n = nlane + nt * 8;
            uint32_t bh0 = Wp_hi[fkk    ][n];
            uint32_t bh1 = Wp_hi[fkk + 4][n];
            uint32_t bl0 = Wp_lo[fkk    ][n];
            uint32_t bl1 = Wp_lo[fkk + 4][n];
            mma_bf16(c[nt][0], c[nt][1], c[nt][2], c[nt][3],
                     ah0, ah1, ah2, ah3, bh0, bh1);
            mma_bf16(c[nt][0], c[nt][1], c[nt][2], c[nt][3],
                     al0, al1, al2, al3, bh0, bh1);
            mma_bf16(c[nt][0], c[nt][1], c[nt][2], c[nt][3],
                     ah0, ah1, ah2, ah3, bl0, bl1);
        }
        __syncthreads();
    }

    // ---- epilogue: bias + store ---------------------------------------------
    float*       C  = wn ? C1 : C0;
    const float* bb = wn ? b1 : b0;
    const int r0 = rowBase + wm * 16 + (lane >> 2);
    const int r1 = r0 + 8;
    #pragma unroll
    for (int nt = 0; nt < 16; nt++) {
        int colc = nt * 8 + 2 * (lane & 3);
        float bx = bb[colc], by = bb[colc + 1];
        if (r0 < N) {
            float2 o = make_float2(c[nt][0] + bx, c[nt][1] + by);
            *reinterpret_cast<float2*>(C + (size_t)r0 * 128 + colc) = o;
        }
        if (r1 < N) {
            float2 o = make_float2(c[nt][2] + bx, c[nt][3] + by);
            *reinterpret_cast<float2*>(C + (size_t)r1 * 128 + colc) = o;
        }
    }
}

// ---------------- small dual GEMM (FFMA2, R6 exact) --------------------------
template<int BN, int TM, int TN, int MAXB>
__global__ void __launch_bounds__(256, MAXB)
gemm_dual_k128(const float* __restrict__ A,
               const float* __restrict__ W0, const float* __restrict__ b0,
               const float* __restrict__ W1, const float* __restrict__ b1,
               float* __restrict__ C0, float* __restrict__ C1,
               int N, int relu_in)
{
    constexpr int K = 128, KC = 32;
    constexpr int TCOLS = (2 * BN) / TN;
    constexpr int TROWS = 256 / TCOLS;
    constexpr int BM = TROWS * TM;

    __shared__ __align__(16) float As[KC][BM + 4];
    __shared__ __align__(16) float Wsm[KC][2 * BN];

    const int t  = threadIdx.x;
    const int tx = t % TCOLS;
    const int ty = t / TCOLS;
    const int rowBase = blockIdx.x * BM;

    unsigned long long acc2[TM / 2][TN];
    #pragma unroll
    for (int i = 0; i < TM / 2; i++)
        #pragma unroll
        for (int j = 0; j < TN; j++) acc2[i][j] = 0ull;

    for (int kc = 0; kc < K; kc += KC) {
        #pragma unroll
        for (int i = 0; i < (BM * KC) / (256 * 4); ++i) {
            int fi = t + i * 256;
            int r  = fi / (KC / 4);
            int c4 = fi % (KC / 4);
            int gr = rowBase + r;
            float4 v = make_float4(0.f, 0.f, 0.f, 0.f);
            if (gr < N) {
                v = reinterpret_cast<const float4*>(A + (size_t)gr * K + kc)[c4];
                if (relu_in) {
                    v.x = fmaxf(v.x, 0.f); v.y = fmaxf(v.y, 0.f);
                    v.z = fmaxf(v.z, 0.f); v.w = fmaxf(v.w, 0.f);
                }
            }
            As[c4 * 4 + 0][r] = v.x;
            As[c4 * 4 + 1][r] = v.y;
            As[c4 * 4 + 2][r] = v.z;
            As[c4 * 4 + 3][r] = v.w;
        }
        #pragma unroll
        for (int i = 0; i < (KC * 2 * BN) / (256 * 4); ++i) {
            int fi = t + i * 256;
            int r  = fi / ((2 * BN) / 4);
            int c4 = fi % ((2 * BN) / 4);
            int col = c4 * 4;
            float4 v;
            if (col < BN) v = reinterpret_cast<const float4*>(W0 + (size_t)(kc + r) * BN + col)[0];
            else          v = reinterpret_cast<const float4*>(W1 + (size_t)(kc + r) * BN + (col - BN))[0];
            reinterpret_cast<float4*>(&Wsm[r][0])[c4] = v;
        }
        __syncthreads();

        #pragma unroll
        for (int k = 0; k < KC; k++) {
            unsigned long long ap[TM / 2];
            #pragma unroll
            for (int i = 0; i < TM / 4; i++) {
                ulonglong2 q = *reinterpret_cast<const ulonglong2*>(&As[k][ty * TM + i * 4]);
                ap[i * 2 + 0] = q.x;
                ap[i * 2 + 1] = q.y;
            }
            unsigned long long wd[TN];
            #pragma unroll
            for (int j = 0; j < TN / 4; j++) {
                float4 w = *reinterpret_cast<const float4*>(&Wsm[k][tx * TN + j * 4]);
                wd[j * 4 + 0] = pack2(w.x, w.x);
                wd[j * 4 + 1] = pack2(w.y, w.y);
                wd[j * 4 + 2] = pack2(w.z, w.z);
                wd[j * 4 + 3] = pack2(w.w, w.w);
            }
            #pragma unroll
            for (int i = 0; i < TM / 2; i++)
                #pragma unroll
                for (int j = 0; j < TN; j++)
                    acc2[i][j] = fma2(ap[i], wd[j], acc2[i][j]);
        }
        __syncthreads();
    }

    const int half = (tx * TN) / BN;
    const int col  = (tx * TN) % BN;
    float*       C  = half ? C1 : C0;
    const float* bb = half ? b1 : b0;
    float bias[TN];
    #pragma unroll
    for (int j = 0; j < TN; j++) bias[j] = bb[col + j];

    #pragma unroll
    for (int i = 0; i < TM / 2; i++) {
        float lo[TN], hi[TN];
        #pragma unroll
        for (int j = 0; j < TN; j++) unpack2(acc2[i][j], lo[j], hi[j]);
        int gr0 = rowBase + ty * TM + 2 * i;
        int gr1 = gr0 + 1;
        if (gr0 < N) {
            #pragma unroll
            for (int j = 0; j < TN / 4; j++) {
                float4 o = make_float4(lo[j*4+0] + bias[j*4+0], lo[j*4+1] + bias[j*4+1],
                                       lo[j*4+2] + bias[j*4+2], lo[j*4+3] + bias[j*4+3]);
                *reinterpret_cast<float4*>(C + (size_t)gr0 * BN + col + j * 4) = o;
            }
        }
        if (gr1 < N) {
            #pragma unroll
            for (int j = 0; j < TN / 4; j++) {
                float4 o = make_float4(hi[j*4+0] + bias[j*4+0], hi[j*4+1] + bias[j*4+1],
                                       hi[j*4+2] + bias[j*4+2], hi[j*4+3] + bias[j*4+3]);
                *reinterpret_cast<float4*>(C + (size_t)gr1 * BN + col + j * 4) = o;
            }
        }
    }
}

// ========== CSR edge aggregation, H=4: warp per dst, prefetch depth 2 =======
__global__ void edge_csr4(const int* __restrict__ rowptr, const int* __restrict__ ssrc,
                          const float* __restrict__ fs, const float* __restrict__ fd,
                          const float* __restrict__ a, float* __restrict__ out, int N)
{
    const int lane = threadIdx.x & 31;
    const int d    = (blockIdx.x * blockDim.x + threadIdx.x) >> 5;
    if (d >= N) return;

    const float4* fs4 = reinterpret_cast<const float4*>(fs);
    float4 v  = reinterpret_cast<const float4*>(fd)[(size_t)d * 32 + lane];
    float4 av = reinterpret_cast<const float4*>(a)[lane];

    float4 acc = make_float4(0.f, 0.f, 0.f, 0.f);
    float den = 0.f;

    const int start = rowptr[d];
    const int end   = rowptr[d + 1];
    if (start < end) {
        const int last = end - 1;
        int i1 = min(start + 1, last);
        float4 u0 = fs4[(size_t)__ldg(ssrc + start) * 32 + lane];
        float4 u1 = fs4[(size_t)__ldg(ssrc + i1)    * 32 + lane];
        for (int i = start; i < end; i++) {
            float4 u = u0;
            u0 = u1;
            int nx = min(i + 2, last);                 // clamped prefetch (depth 2)
            u1 = fs4[(size_t)__ldg(ssrc + nx) * 32 + lane];
            float p = lrelu(u.x + v.x) * av.x + lrelu(u.y + v.y) * av.y
                    + lrelu(u.z + v.z) * av.z + lrelu(u.w + v.w) * av.w;
            p += __shfl_xor_sync(0xffffffffu, p, 1);
            p += __shfl_xor_sync(0xffffffffu, p, 2);
            p += __shfl_xor_sync(0xffffffffu, p, 4);
            float ex = __expf(p);    // softmax shift-invariant; logits are O(1)
            acc.x = fmaf(u.x, ex, acc.x);
            acc.y = fmaf(u.y, ex, acc.y);
            acc.z = fmaf(u.z, ex, acc.z);
            acc.w = fmaf(u.w, ex, acc.w);
            den += ex;
        }
    }
    float sc = (den > 0.f) ? 1.0f / den : 0.f;   // zero-degree -> zeros
    acc.x *= sc; acc.y *= sc; acc.z *= sc; acc.w *= sc;
    reinterpret_cast<float4*>(out)[(size_t)d * 32 + lane] = acc;
}

// ========== CSR edge aggregation, H=1 (32 feats): warp=dst, 4 edge slots ====
__global__ void edge_csr1(const int* __restrict__ rowptr, const int* __restrict__ ssrc,
                          const float* __restrict__ fs, const float* __restrict__ fd,
                          const float* __restrict__ a, float* __restrict__ out, int N)
{
    const int lane = threadIdx.x & 31;
    const int d    = (blockIdx.x * blockDim.x + threadIdx.x) >> 5;
    if (d >= N) return;
    const int slot = lane >> 3;
    const int sub  = lane & 7;

    const float4* fs4 = reinterpret_cast<const float4*>(fs);
    float4 v  = reinterpret_cast<const float4*>(fd)[(size_t)d * 8 + sub];
    float4 av = reinterpret_cast<const float4*>(a)[sub];

    float4 acc = make_float4(0.f, 0.f, 0.f, 0.f);
    float den = 0.f;

    const int start = rowptr[d];
    const int end   = rowptr[d + 1];
    const int iters = (end - start + 3) >> 2;

    int idx0 = start + slot;
    float4 un = make_float4(0.f, 0.f, 0.f, 0.f);
    if (idx0 < end) un = fs4[(size_t)__ldg(ssrc + idx0) * 8 + sub];

    for (int it = 0; it < iters; it++) {
        bool ok = (start + it * 4 + slot) < end;
        float4 u = un;
        int nidx = start + (it + 1) * 4 + slot;
        if (nidx < end) un = fs4[(size_t)__ldg(ssrc + nidx) * 8 + sub];
        else            un = make_float4(0.f, 0.f, 0.f, 0.f);

        float p = lrelu(u.x + v.x) * av.x + lrelu(u.y + v.y) * av.y
                + lrelu(u.z + v.z) * av.z + lrelu(u.w + v.w) * av.w;
        p += __shfl_xor_sync(0xffffffffu, p, 1);
        p += __shfl_xor_sync(0xffffffffu, p, 2);
        p += __shfl_xor_sync(0xffffffffu, p, 4);
        float ex = ok ? __expf(p) : 0.f;
        acc.x = fmaf(u.x, ex, acc.x);
        acc.y = fmaf(u.y, ex, acc.y);
        acc.z = fmaf(u.z, ex, acc.z);
        acc.w = fmaf(u.w, ex, acc.w);
        den += ex;
    }
    #pragma unroll
    for (int m = 8; m <= 16; m <<= 1) {
        acc.x += __shfl_xor_sync(0xffffffffu, acc.x, m);
        acc.y += __shfl_xor_sync(0xffffffffu, acc.y, m);
        acc.z += __shfl_xor_sync(0xffffffffu, acc.z, m);
        acc.w += __shfl_xor_sync(0xffffffffu, acc.w, m);
        den   += __shfl_xor_sync(0xffffffffu, den,   m);
    }
    if (slot == 0) {
        float sc = (den > 0.f) ? 1.0f / den : 0.f;
        acc.x *= sc; acc.y *= sc; acc.z *= sc; acc.w *= sc;
        reinterpret_cast<float4*>(out)[(size_t)d * 8 + sub] = acc;
    }
}

// ---------------- launch -----------------------------------------------------
extern "C" void kernel_launch(void* const* d_in, const int* in_sizes, int n_in,
                              void* d_out, int out_size)
{
    const float* feat = (const float*)d_in[0];
    const int*   src  = (const int*)d_in[1];
    const int*   dst  = (const int*)d_in[2];
    const float* Ws0 = (const float*)d_in[3];  const float* bs0 = (const float*)d_in[4];
    const float* Wd0 = (const float*)d_in[5];  const float* bd0 = (const float*)d_in[6];
    const float* a0  = (const float*)d_in[7];
    const float* Ws1 = (const float*)d_in[8];  const float* bs1 = (const float*)d_in[9];
    const float* Wd1 = (const float*)d_in[10]; const float* bd1 = (const float*)d_in[11];
    const float* a1  = (const float*)d_in[12];
    const float* Ws2 = (const float*)d_in[13]; const float* bs2 = (const float*)d_in[14];
    const float* Wd2 = (const float*)d_in[15]; const float* bd2 = (const float*)d_in[16];
    const float* a2  = (const float*)d_in[17];
    float* out = (float*)d_out;

    const int N = in_sizes[0] / 128;
    const int E = in_sizes[1];

    float *fs, *fd, *h;
    int *hist, *rowptr, *woff, *ssrc;
    uint32_t *wh0, *wl0, *wh1, *wl1;
    cudaGetSymbolAddress((void**)&fs,     g_fs);
    cudaGetSymbolAddress((void**)&fd,     g_fd);
    cudaGetSymbolAddress((void**)&h,      g_h);
    cudaGetSymbolAddress((void**)&hist,   g_hist);
    cudaGetSymbolAddress((void**)&rowptr, g_rowptr);
    cudaGetSymbolAddress((void**)&woff,   g_woff);
    cudaGetSymbolAddress((void**)&ssrc,   g_ssrc);
    cudaGetSymbolAddress((void**)&wh0,    g_wh0);
    cudaGetSymbolAddress((void**)&wl0,    g_wl0);
    cudaGetSymbolAddress((void**)&wh1,    g_wh1);
    cudaGetSymbolAddress((void**)&wl1,    g_wl1);

    const int gemmGridBig   = (N + 63) / 64;   // BM=64, mma kernel
    const int gemmGridSmall = (N + 63) / 64;   // BM=64 (TM=4, TN=4)
    const int edgeGrid = (N * 32 + 255) / 256; // one warp per dst
    const int E4 = E / 4;
    const int eg4 = (E4 + 255) / 256;

    // ---- W preconversion + CSR build (graph topology fixed across layers) --
    conv_w<<<64, 256>>>(Ws0, Wd0, wh0, wl0);
    conv_w<<<64, 256>>>(Ws1, Wd1, wh1, wl1);
    cudaMemsetAsync(hist, 0, (size_t)N * sizeof(int));
    hist_count4<<<eg4, 256>>>(dst, hist, E4);
    scan_hist<<<1, 1024>>>(hist, rowptr, woff, N);
    edge_bucket4<<<eg4, 256>>>(src, dst, woff, ssrc, E4);

    // ---- layer 0 (input 128 -> 4x32) ----
    gemm_dual_mma<<<gemmGridBig, 256>>>(feat, wh0, wl0, bs0, bd0, fs, fd, N, 0);
    edge_csr4<<<edgeGrid, 256>>>(rowptr, ssrc, fs, fd, a0, h, N);

    // ---- layer 1 (ReLU(h) 128 -> 4x32) ----
    gemm_dual_mma<<<gemmGridBig, 256>>>(h, wh1, wl1, bs1, bd1, fs, fd, N, 1);
    edge_csr4<<<edgeGrid, 256>>>(rowptr, ssrc, fs, fd, a1, h, N);

    // ---- layer 2 (ReLU(h) 128 -> 1x32), mean over 1 head == identity ----
    gemm_dual_k128<32, 4, 4, 2><<<gemmGridSmall, 256>>>(h, Ws2, bs2, Wd2, bd2, fs, fd, N, 1);
    edge_csr1<<<edgeGrid, 256>>>(rowptr, ssrc, fs, fd, a2, out, N);
}

// round 17
// speedup vs baseline: 1.5379x; 1.2197x over previous
#include <cuda_runtime.h>
#include <cstdint>

#define NNODES 50000
#define NEDGES 800000

// ---------------- scratch (device globals; no allocation allowed) ----------
__device__ float g_fs[NNODES * 128];
__device__ float g_fd[NNODES * 128];
__device__ float g_h [NNODES * 128];
__device__ int   g_hist[NNODES];
__device__ int   g_rowptr[NNODES + 1];
__device__ int   g_woff[NNODES];
__device__ int   g_ssrc[NEDGES];
__device__ int   g_bsum[256];
__device__ int   g_boff[256];
// preconverted W (bf16x2 hi/lo, [kpair][256] layout), layers 0 and 1
__device__ uint32_t g_wh0[64 * 256];
__device__ uint32_t g_wl0[64 * 256];
__device__ uint32_t g_wh1[64 * 256];
__device__ uint32_t g_wl1[64 * 256];

__device__ __forceinline__ float lrelu(float x) { return x > 0.f ? x : 0.2f * x; }

// ---- packed f32x2 helpers (FFMA2, small GEMM only) -------------------------
__device__ __forceinline__ unsigned long long pack2(float lo, float hi) {
    unsigned long long r;
    asm("mov.b64 %0, {%1, %2};" : "=l"(r) : "f"(lo), "f"(hi));
    return r;
}
__device__ __forceinline__ void unpack2(unsigned long long v, float& lo, float& hi) {
    asm("mov.b64 {%0, %1}, %2;" : "=f"(lo), "=f"(hi) : "l"(v));
}
__device__ __forceinline__ unsigned long long fma2(unsigned long long a,
                                                   unsigned long long b,
                                                   unsigned long long c) {
    unsigned long long d;
    asm("fma.rn.f32x2 %0, %1, %2, %3;" : "=l"(d) : "l"(a), "l"(b), "l"(c));
    return d;
}

// ---- bf16 helpers ----------------------------------------------------------
__device__ __forceinline__ uint32_t bf16_bits_rn(float x) {   // bf16 in high 16
    uint32_t u = __float_as_uint(x);
    return (u + 0x7fffu + ((u >> 16) & 1u)) & 0xffff0000u;
}
__device__ __forceinline__ uint32_t bf16pack(uint32_t bits_even, uint32_t bits_odd) {
    return bits_odd | (bits_even >> 16);
}
__device__ __forceinline__ void mma_bf16(float& d0, float& d1, float& d2, float& d3,
                                         uint32_t a0, uint32_t a1, uint32_t a2, uint32_t a3,
                                         uint32_t b0, uint32_t b1) {
    asm volatile("mma.sync.aligned.m16n8k16.row.col.f32.bf16.bf16.f32 "
                 "{%0,%1,%2,%3}, {%4,%5,%6,%7}, {%8,%9}, {%0,%1,%2,%3};"
                 : "+f"(d0), "+f"(d1), "+f"(d2), "+f"(d3)
                 : "r"(a0), "r"(a1), "r"(a2), "r"(a3), "r"(b0), "r"(b1));
}

// ---- W preconversion: fp32 [128,128]x2 -> packed bf16x2 hi/lo [64][256] ----
__global__ void conv_w(const float* __restrict__ W0, const float* __restrict__ W1,
                       uint32_t* __restrict__ wh, uint32_t* __restrict__ wl)
{
    int idx = blockIdx.x * 256 + threadIdx.x;   // 16384 total
    int kp  = idx >> 8;
    int n   = idx & 255;
    const float* Wb = (n < 128) ? W0 : W1;
    int nn = n & 127;
    float w0 = Wb[(size_t)(2 * kp)     * 128 + nn];
    float w1 = Wb[(size_t)(2 * kp + 1) * 128 + nn];
    uint32_t h0 = bf16_bits_rn(w0), h1 = bf16_bits_rn(w1);
    float r0 = w0 - __uint_as_float(h0);
    float r1 = w1 - __uint_as_float(h1);
    wh[idx] = bf16pack(h0, h1);
    wl[idx] = bf16pack(bf16_bits_rn(r0), bf16_bits_rn(r1));
}

// ================= CSR construction (once per launch, reused 3x) ============
__global__ void hist_count4(const int* __restrict__ dst, int* hist, int E4) {
    int i = blockIdx.x * blockDim.x + threadIdx.x;
    if (i < E4) {
        int4 d = reinterpret_cast<const int4*>(dst)[i];
        atomicAdd(&hist[d.x], 1);
        atomicAdd(&hist[d.y], 1);
        atomicAdd(&hist[d.z], 1);
        atomicAdd(&hist[d.w], 1);
    }
}
// ---- multi-block exclusive scan: phase 1 — per-block sums ----
__global__ void scan_blk_sum(const int* __restrict__ hist, int* bsum, int n) {
    __shared__ int sm[256];
    int t = threadIdx.x;
    int i = blockIdx.x * 256 + t;
    sm[t] = (i < n) ? hist[i] : 0;
    __syncthreads();
    #pragma unroll
    for (int d = 128; d > 0; d >>= 1) {
        if (t < d) sm[t] += sm[t + d];
        __syncthreads();
    }
    if (t == 0) bsum[blockIdx.x] = sm[0];
}
// ---- phase 2 — scan the (<=256) block sums; also writes rowptr[n] ----
__global__ void scan_bsum(const int* __restrict__ bsum, int* boff,
                          int nb, int* rowptr, int n) {
    __shared__ int sm[256];
    int t = threadIdx.x;
    int v = (t < nb) ? bsum[t] : 0;
    sm[t] = v;
    __syncthreads();
    #pragma unroll
    for (int d = 1; d < 256; d <<= 1) {
        int x = (t >= d) ? sm[t - d] : 0;
        __syncthreads();
        sm[t] += x;
        __syncthreads();
    }
    if (t < nb) boff[t] = sm[t] - v;          // exclusive prefix of block sums
    if (t == nb - 1) rowptr[n] = sm[t];       // total
}
// ---- phase 3 — per-block scan + global offset -> rowptr / woff ----
__global__ void scan_final(const int* __restrict__ hist, const int* __restrict__ boff,
                           int* rowptr, int* woff, int n) {
    __shared__ int sm[256];
    int t = threadIdx.x;
    int i = blockIdx.x * 256 + t;
    int v = (i < n) ? hist[i] : 0;
    sm[t] = v;
    __syncthreads();
    #pragma unroll
    for (int d = 1; d < 256; d <<= 1) {
        int x = (t >= d) ? sm[t - d] : 0;
        __syncthreads();
        sm[t] += x;
        __syncthreads();
    }
    if (i < n) {
        int off = boff[blockIdx.x] + sm[t] - v;   // exclusive
        rowptr[i] = off;
        woff[i]   = off;
    }
}
__global__ void edge_bucket4(const int* __restrict__ src, const int* __restrict__ dst,
                             int* woff, int* ssrc, int E4) {
    int i = blockIdx.x * blockDim.x + threadIdx.x;
    if (i < E4) {
        int4 d = reinterpret_cast<const int4*>(dst)[i];
        int4 s = reinterpret_cast<const int4*>(src)[i];
        int p0 = atomicAdd(&woff[d.x], 1);
        int p1 = atomicAdd(&woff[d.y], 1);
        int p2 = atomicAdd(&woff[d.z], 1);
        int p3 = atomicAdd(&woff[d.w], 1);
        ssrc[p0] = s.x;
        ssrc[p1] = s.y;
        ssrc[p2] = s.z;
        ssrc[p3] = s.w;
    }
}

// ====== BIG dual GEMM via tensor cores (bf16 mma.sync, 3-term split) ========
// W comes PRECONVERTED (g_wh/g_wl) — only A is split per-block.
__global__ void __launch_bounds__(256, 2)
gemm_dual_mma(const float* __restrict__ A,
              const uint32_t* __restrict__ wh, const uint32_t* __restrict__ wl,
              const float* __restrict__ b0, const float* __restrict__ b1,
              float* __restrict__ C0, float* __restrict__ C1,
              int N, int relu_in)
{
    constexpr int K = 128, KC = 16, NCH = K / KC;   // 8 chunks
    __shared__ uint32_t Ap_hi[64][12], Ap_lo[64][12];
    __shared__ uint32_t Wp_hi[8][264], Wp_lo[8][264];

    const int t    = threadIdx.x;
    const int lane = t & 31;
    const int warp = t >> 5;
    const int wm   = warp >> 1;
    const int wn   = warp & 1;
    const int rowBase = blockIdx.x * 64;

    float c[16][4];
    #pragma unroll
    for (int i = 0; i < 16; i++)
        #pragma unroll
        for (int j = 0; j < 4; j++) c[i][j] = 0.f;

    const int arow = t >> 2;
    const int akk  = t & 3;

    for (int ch = 0; ch < NCH; ch++) {
        const int kc = ch * KC;
        {
            int gr = rowBase + arow;
            #pragma unroll
            for (int q = 0; q < 2; q++) {
                int kk = akk + q * 4;
                float2 v = make_float2(0.f, 0.f);
                if (gr < N)
                    v = *reinterpret_cast<const float2*>(A + (size_t)gr * K + kc + 2 * kk);
                if (relu_in) { v.x = fmaxf(v.x, 0.f); v.y = fmaxf(v.y, 0.f); }
                uint32_t hx = bf16_bits_rn(v.x), hy = bf16_bits_rn(v.y);
                float rx = v.x - __uint_as_float(hx);
                float ry = v.y - __uint_as_float(hy);
                Ap_hi[arow][kk] = bf16pack(hx, hy);
                Ap_lo[arow][kk] = bf16pack(bf16_bits_rn(rx), bf16_bits_rn(ry));
            }
        }
        {
            const uint32_t* whc = wh + (size_t)ch * 8 * 256;
            const uint32_t* wlc = wl + (size_t)ch * 8 * 256;
            #pragma unroll
            for (int i = 0; i < 8; i++) {
                int fi = t + i * 256;
                int kk = fi >> 8;
                int n  = fi & 255;
                Wp_hi[kk][n] = whc[fi];
                Wp_lo[kk][n] = wlc[fi];
            }
        }
        __syncthreads();

        const int frow = wm * 16 + (lane >> 2);
        const int fkk  = lane & 3;
        uint32_t ah0 = Ap_hi[frow    ][fkk    ];
        uint32_t ah1 = Ap_hi[frow + 8][fkk    ];
        uint32_t ah2 = Ap_hi[frow    ][fkk + 4];
        uint32_t ah3 = Ap_hi[frow + 8][fkk + 4];
        uint32_t al0 = Ap_lo[frow    ][fkk    ];
        uint32_t al1 = Ap_lo[frow + 8][fkk    ];
        uint32_t al2 = Ap_lo[frow    ][fkk + 4];
        uint32_t al3 = Ap_lo[frow + 8][fkk + 4];

        const int nlane = wn * 128 + (lane >> 2);
        #pragma unroll
        for (int nt = 0; nt < 16; nt++) {
            int n = nlane + nt * 8;
            uint32_t bh0 = Wp_hi[fkk    ][n];
            uint32_t bh1 = Wp_hi[fkk + 4][n];
            uint32_t bl0 = Wp_lo[fkk    ][n];
            uint32_t bl1 = Wp_lo[fkk + 4][n];
            mma_bf16(c[nt][0], c[nt][1], c[nt][2], c[nt][3],
                     ah0, ah1, ah2, ah3, bh0, bh1);
            mma_bf16(c[nt][0], c[nt][1], c[nt][2], c[nt][3],
                     al0, al1, al2, al3, bh0, bh1);
            mma_bf16(c[nt][0], c[nt][1], c[nt][2], c[nt][3],
                     ah0, ah1, ah2, ah3, bl0, bl1);
        }
        __syncthreads();
    }

    float*       C  = wn ? C1 : C0;
    const float* bb = wn ? b1 : b0;
    const int r0 = rowBase + wm * 16 + (lane >> 2);
    const int r1 = r0 + 8;
    #pragma unroll
    for (int nt = 0; nt < 16; nt++) {
        int colc = nt * 8 + 2 * (lane & 3);
        float bx = bb[colc], by = bb[colc + 1];
        if (r0 < N) {
            float2 o = make_float2(c[nt][0] + bx, c[nt][1] + by);
            *reinterpret_cast<float2*>(C + (size_t)r0 * 128 + colc) = o;
        }
        if (r1 < N) {
            float2 o = make_float2(c[nt][2] + bx, c[nt][3] + by);
            *reinterpret_cast<float2*>(C + (size_t)r1 * 128 + colc) = o;
        }
    }
}

// ---------------- small dual GEMM (FFMA2, R6 exact) --------------------------
template<int BN, int TM, int TN, int MAXB>
__global__ void __launch_bounds__(256, MAXB)
gemm_dual_k128(const float* __restrict__ A,
               const float* __restrict__ W0, const float* __restrict__ b0,
               const float* __restrict__ W1, const float* __restrict__ b1,
               float* __restrict__ C0, float* __restrict__ C1,
               int N, int relu_in)
{
    constexpr int K = 128, KC = 32;
    constexpr int TCOLS = (2 * BN) / TN;
    constexpr int TROWS = 256 / TCOLS;
    constexpr int BM = TROWS * TM;

    __shared__ __align__(16) float As[KC][BM + 4];
    __shared__ __align__(16) float Wsm[KC][2 * BN];

    const int t  = threadIdx.x;
    const int tx = t % TCOLS;
    const int ty = t / TCOLS;
    const int rowBase = blockIdx.x * BM;

    unsigned long long acc2[TM / 2][TN];
    #pragma unroll
    for (int i = 0; i < TM / 2; i++)
        #pragma unroll
        for (int j = 0; j < TN; j++) acc2[i][j] = 0ull;

    for (int kc = 0; kc < K; kc += KC) {
        #pragma unroll
        for (int i = 0; i < (BM * KC) / (256 * 4); ++i) {
            int fi = t + i * 256;
            int r  = fi / (KC / 4);
            int c4 = fi % (KC / 4);
            int gr = rowBase + r;
            float4 v = make_float4(0.f, 0.f, 0.f, 0.f);
            if (gr < N) {
                v = reinterpret_cast<const float4*>(A + (size_t)gr * K + kc)[c4];
                if (relu_in) {
                    v.x = fmaxf(v.x, 0.f); v.y = fmaxf(v.y, 0.f);
                    v.z = fmaxf(v.z, 0.f); v.w = fmaxf(v.w, 0.f);
                }
            }
            As[c4 * 4 + 0][r] = v.x;
            As[c4 * 4 + 1][r] = v.y;
            As[c4 * 4 + 2][r] = v.z;
            As[c4 * 4 + 3][r] = v.w;
        }
        #pragma unroll
        for (int i = 0; i < (KC * 2 * BN) / (256 * 4); ++i) {
            int fi = t + i * 256;
            int r  = fi / ((2 * BN) / 4);
            int c4 = fi % ((2 * BN) / 4);
            int col = c4 * 4;
            float4 v;
            if (col < BN) v = reinterpret_cast<const float4*>(W0 + (size_t)(kc + r) * BN + col)[0];
            else          v = reinterpret_cast<const float4*>(W1 + (size_t)(kc + r) * BN + (col - BN))[0];
            reinterpret_cast<float4*>(&Wsm[r][0])[c4] = v;
        }
        __syncthreads();

        #pragma unroll
        for (int k = 0; k < KC; k++) {
            unsigned long long ap[TM / 2];
            #pragma unroll
            for (int i = 0; i < TM / 4; i++) {
                ulonglong2 q = *reinterpret_cast<const ulonglong2*>(&As[k][ty * TM + i * 4]);
                ap[i * 2 + 0] = q.x;
                ap[i * 2 + 1] = q.y;
            }
            unsigned long long wd[TN];
            #pragma unroll
            for (int j = 0; j < TN / 4; j++) {
                float4 w = *reinterpret_cast<const float4*>(&Wsm[k][tx * TN + j * 4]);
                wd[j * 4 + 0] = pack2(w.x, w.x);
                wd[j * 4 + 1] = pack2(w.y, w.y);
                wd[j * 4 + 2] = pack2(w.z, w.z);
                wd[j * 4 + 3] = pack2(w.w, w.w);
            }
            #pragma unroll
            for (int i = 0; i < TM / 2; i++)
                #pragma unroll
                for (int j = 0; j < TN; j++)
                    acc2[i][j] = fma2(ap[i], wd[j], acc2[i][j]);
        }
        __syncthreads();
    }

    const int half = (tx * TN) / BN;
    const int col  = (tx * TN) % BN;
    float*       C  = half ? C1 : C0;
    const float* bb = half ? b1 : b0;
    float bias[TN];
    #pragma unroll
    for (int j = 0; j < TN; j++) bias[j] = bb[col + j];

    #pragma unroll
    for (int i = 0; i < TM / 2; i++) {
        float lo[TN], hi[TN];
        #pragma unroll
        for (int j = 0; j < TN; j++) unpack2(acc2[i][j], lo[j], hi[j]);
        int gr0 = rowBase + ty * TM + 2 * i;
        int gr1 = gr0 + 1;
        if (gr0 < N) {
            #pragma unroll
            for (int j = 0; j < TN / 4; j++) {
                float4 o = make_float4(lo[j*4+0] + bias[j*4+0], lo[j*4+1] + bias[j*4+1],
                                       lo[j*4+2] + bias[j*4+2], lo[j*4+3] + bias[j*4+3]);
                *reinterpret_cast<float4*>(C + (size_t)gr0 * BN + col + j * 4) = o;
            }
        }
        if (gr1 < N) {
            #pragma unroll
            for (int j = 0; j < TN / 4; j++) {
                float4 o = make_float4(hi[j*4+0] + bias[j*4+0], hi[j*4+1] + bias[j*4+1],
                                       hi[j*4+2] + bias[j*4+2], hi[j*4+3] + bias[j*4+3]);
                *reinterpret_cast<float4*>(C + (size_t)gr1 * BN + col + j * 4) = o;
            }
        }
    }
}

// ========== CSR edge aggregation, H=4: warp per dst, prefetch depth 2 =======
__global__ void edge_csr4(const int* __restrict__ rowptr, const int* __restrict__ ssrc,
                          const float* __restrict__ fs, const float* __restrict__ fd,
                          const float* __restrict__ a, float* __restrict__ out, int N)
{
    const int lane = threadIdx.x & 31;
    const int d    = (blockIdx.x * blockDim.x + threadIdx.x) >> 5;
    if (d >= N) return;

    const float4* fs4 = reinterpret_cast<const float4*>(fs);
    float4 v  = reinterpret_cast<const float4*>(fd)[(size_t)d * 32 + lane];
    float4 av = reinterpret_cast<const float4*>(a)[lane];

    float4 acc = make_float4(0.f, 0.f, 0.f, 0.f);
    float den = 0.f;

    const int start = rowptr[d];
    const int end   = rowptr[d + 1];
    if (start < end) {
        const int last = end - 1;
        int i1 = min(start + 1, last);
        float4 u0 = fs4[(size_t)__ldg(ssrc + start) * 32 + lane];
        float4 u1 = fs4[(size_t)__ldg(ssrc + i1)    * 32 + lane];
        for (int i = start; i < end; i++) {
            float4 u = u0;
            u0 = u1;
            int nx = min(i + 2, last);                 // clamped prefetch (depth 2)
            u1 = fs4[(size_t)__ldg(ssrc + nx) * 32 + lane];
            float p = lrelu(u.x + v.x) * av.x + lrelu(u.y + v.y) * av.y
                    + lrelu(u.z + v.z) * av.z + lrelu(u.w + v.w) * av.w;
            p += __shfl_xor_sync(0xffffffffu, p, 1);
            p += __shfl_xor_sync(0xffffffffu, p, 2);
            p += __shfl_xor_sync(0xffffffffu, p, 4);
            float ex = __expf(p);    // softmax shift-invariant; logits are O(1)
            acc.x = fmaf(u.x, ex, acc.x);
            acc.y = fmaf(u.y, ex, acc.y);
            acc.z = fmaf(u.z, ex, acc.z);
            acc.w = fmaf(u.w, ex, acc.w);
            den += ex;
        }
    }
    float sc = (den > 0.f) ? 1.0f / den : 0.f;   // zero-degree -> zeros
    acc.x *= sc; acc.y *= sc; acc.z *= sc; acc.w *= sc;
    reinterpret_cast<float4*>(out)[(size_t)d * 32 + lane] = acc;
}

// ========== CSR edge aggregation, H=1 (32 feats): warp=dst, 4 edge slots ====
__global__ void edge_csr1(const int* __restrict__ rowptr, const int* __restrict__ ssrc,
                          const float* __restrict__ fs, const float* __restrict__ fd,
                          const float* __restrict__ a, float* __restrict__ out, int N)
{
    const int lane = threadIdx.x & 31;
    const int d    = (blockIdx.x * blockDim.x + threadIdx.x) >> 5;
    if (d >= N) return;
    const int slot = lane >> 3;
    const int sub  = lane & 7;

    const float4* fs4 = reinterpret_cast<const float4*>(fs);
    float4 v  = reinterpret_cast<const float4*>(fd)[(size_t)d * 8 + sub];
    float4 av = reinterpret_cast<const float4*>(a)[sub];

    float4 acc = make_float4(0.f, 0.f, 0.f, 0.f);
    float den = 0.f;

    const int start = rowptr[d];
    const int end   = rowptr[d + 1];
    const int iters = (end - start + 3) >> 2;

    int idx0 = start + slot;
    float4 un = make_float4(0.f, 0.f, 0.f, 0.f);
    if (idx0 < end) un = fs4[(size_t)__ldg(ssrc + idx0) * 8 + sub];

    for (int it = 0; it < iters; it++) {
        bool ok = (start + it * 4 + slot) < end;
        float4 u = un;
        int nidx = start + (it + 1) * 4 + slot;
        if (nidx < end) un = fs4[(size_t)__ldg(ssrc + nidx) * 8 + sub];
        else            un = make_float4(0.f, 0.f, 0.f, 0.f);

        float p = lrelu(u.x + v.x) * av.x + lrelu(u.y + v.y) * av.y
                + lrelu(u.z + v.z) * av.z + lrelu(u.w + v.w) * av.w;
        p += __shfl_xor_sync(0xffffffffu, p, 1);
        p += __shfl_xor_sync(0xffffffffu, p, 2);
        p += __shfl_xor_sync(0xffffffffu, p, 4);
        float ex = ok ? __expf(p) : 0.f;
        acc.x = fmaf(u.x, ex, acc.x);
        acc.y = fmaf(u.y, ex, acc.y);
        acc.z = fmaf(u.z, ex, acc.z);
        acc.w = fmaf(u.w, ex, acc.w);
        den += ex;
    }
    #pragma unroll
    for (int m = 8; m <= 16; m <<= 1) {
        acc.x += __shfl_xor_sync(0xffffffffu, acc.x, m);
        acc.y += __shfl_xor_sync(0xffffffffu, acc.y, m);
        acc.z += __shfl_xor_sync(0xffffffffu, acc.z, m);
        acc.w += __shfl_xor_sync(0xffffffffu, acc.w, m);
        den   += __shfl_xor_sync(0xffffffffu, den,   m);
    }
    if (slot == 0) {
        float sc = (den > 0.f) ? 1.0f / den : 0.f;
        acc.x *= sc; acc.y *= sc; acc.z *= sc; acc.w *= sc;
        reinterpret_cast<float4*>(out)[(size_t)d * 8 + sub] = acc;
    }
}

// ---------------- launch -----------------------------------------------------
extern "C" void kernel_launch(void* const* d_in, const int* in_sizes, int n_in,
                              void* d_out, int out_size)
{
    const float* feat = (const float*)d_in[0];
    const int*   src  = (const int*)d_in[1];
    const int*   dst  = (const int*)d_in[2];
    const float* Ws0 = (const float*)d_in[3];  const float* bs0 = (const float*)d_in[4];
    const float* Wd0 = (const float*)d_in[5];  const float* bd0 = (const float*)d_in[6];
    const float* a0  = (const float*)d_in[7];
    const float* Ws1 = (const float*)d_in[8];  const float* bs1 = (const float*)d_in[9];
    const float* Wd1 = (const float*)d_in[10]; const float* bd1 = (const float*)d_in[11];
    const float* a1  = (const float*)d_in[12];
    const float* Ws2 = (const float*)d_in[13]; const float* bs2 = (const float*)d_in[14];
    const float* Wd2 = (const float*)d_in[15]; const float* bd2 = (const float*)d_in[16];
    const float* a2  = (const float*)d_in[17];
    float* out = (float*)d_out;

    const int N = in_sizes[0] / 128;
    const int E = in_sizes[1];

    float *fs, *fd, *h;
    int *hist, *rowptr, *woff, *ssrc, *bsum, *boff;
    uint32_t *wh0, *wl0, *wh1, *wl1;
    cudaGetSymbolAddress((void**)&fs,     g_fs);
    cudaGetSymbolAddress((void**)&fd,     g_fd);
    cudaGetSymbolAddress((void**)&h,      g_h);
    cudaGetSymbolAddress((void**)&hist,   g_hist);
    cudaGetSymbolAddress((void**)&rowptr, g_rowptr);
    cudaGetSymbolAddress((void**)&woff,   g_woff);
    cudaGetSymbolAddress((void**)&ssrc,   g_ssrc);
    cudaGetSymbolAddress((void**)&bsum,   g_bsum);
    cudaGetSymbolAddress((void**)&boff,   g_boff);
    cudaGetSymbolAddress((void**)&wh0,    g_wh0);
    cudaGetSymbolAddress((void**)&wl0,    g_wl0);
    cudaGetSymbolAddress((void**)&wh1,    g_wh1);
    cudaGetSymbolAddress((void**)&wl1,    g_wl1);

    const int gemmGridBig   = (N + 63) / 64;   // BM=64, mma kernel
    const int gemmGridSmall = (N + 63) / 64;   // BM=64 (TM=4, TN=4)
    const int edgeGrid = (N * 32 + 255) / 256; // one warp per dst
    const int E4 = E / 4;
    const int eg4 = (E4 + 255) / 256;
    const int NB = (N + 255) / 256;            // scan blocks (<=256)

    // ---- W preconversion + CSR build (graph topology fixed across layers) --
    conv_w<<<64, 256>>>(Ws0, Wd0, wh0, wl0);
    conv_w<<<64, 256>>>(Ws1, Wd1, wh1, wl1);
    cudaMemsetAsync(hist, 0, (size_t)N * sizeof(int));
    hist_count4<<<eg4, 256>>>(dst, hist, E4);
    scan_blk_sum<<<NB, 256>>>(hist, bsum, N);
    scan_bsum<<<1, 256>>>(bsum, boff, NB, rowptr, N);
    scan_final<<<NB, 256>>>(hist, boff, rowptr, woff, N);
    edge_bucket4<<<eg4, 256>>>(src, dst, woff, ssrc, E4);

    // ---- layer 0 (input 128 -> 4x32) ----
    gemm_dual_mma<<<gemmGridBig, 256>>>(feat, wh0, wl0, bs0, bd0, fs, fd, N, 0);
    edge_csr4<<<edgeGrid, 256>>>(rowptr, ssrc, fs, fd, a0, h, N);

    // ---- layer 1 (ReLU(h) 128 -> 4x32) ----
    gemm_dual_mma<<<gemmGridBig, 256>>>(h, wh1, wl1, bs1, bd1, fs, fd, N, 1);
    edge_csr4<<<edgeGrid, 256>>>(rowptr, ssrc, fs, fd, a1, h, N);

    // ---- layer 2 (ReLU(h) 128 -> 1x32), mean over 1 head == identity ----
    gemm_dual_k128<32, 4, 4, 2><<<gemmGridSmall, 256>>>(h, Ws2, bs2, Wd2, bd2, fs, fd, N, 1);
    edge_csr1<<<edgeGrid, 256>>>(rowptr, ssrc, fs, fd, a2, out, N);
}